// round 6
// baseline (speedup 1.0000x reference)
#include <cuda_runtime.h>
#include <cuda_bf16.h>
#include <math.h>
#include <stdint.h>

#define NB   4
#define LSEQ 2048
#define EMB  1024
#define NH   16
#define HD   64
#define BHN  (NB*NH)
// Q pre-scale: (1/sqrt(EMB)) * log2(e)  -> scores come out in log2 domain
#define QS   (0.04508422f)

// ---------------- scratch ----------------
__device__ __nv_bfloat16 g_qh[BHN*LSEQ*HD];   // [bh][l][d]  (pre-scaled)
__device__ __nv_bfloat16 g_ql[BHN*LSEQ*HD];
__device__ __nv_bfloat16 g_kh[BHN*LSEQ*HD];
__device__ __nv_bfloat16 g_kl[BHN*LSEQ*HD];
__device__ __nv_bfloat16 g_vht[BHN*HD*LSEQ];  // transposed: [bh][d][key]
__device__ __nv_bfloat16 g_vlt[BHN*HD*LSEQ];
__device__ __nv_bfloat16 g_aoh[NB*LSEQ*EMB];  // attention out hi  [token][E]
__device__ __nv_bfloat16 g_aol[NB*LSEQ*EMB];  // attention out lo
__device__ __nv_bfloat16 g_woh[EMB*EMB];      // Wo hi  [e][k]
__device__ __nv_bfloat16 g_wol[EMB*EMB];      // Wo lo

__device__ __forceinline__ uint32_t pack2(__nv_bfloat16 a, __nv_bfloat16 b) {
    return (uint32_t)__bfloat16_as_ushort(a) | ((uint32_t)__bfloat16_as_ushort(b) << 16);
}
__device__ __forceinline__ uint32_t smem_u32(const void* p) {
    uint32_t a;
    asm("{ .reg .u64 t; cvta.to.shared.u64 t, %1; cvt.u32.u64 %0, t; }" : "=r"(a) : "l"(p));
    return a;
}
__device__ __forceinline__ float ex2f(float x) {
    float y; asm("ex2.approx.f32 %0, %1;" : "=f"(y) : "f"(x)); return y;
}
__device__ __forceinline__ void mma16816(float* c, const uint32_t* a,
                                         uint32_t b0, uint32_t b1) {
    asm volatile("mma.sync.aligned.m16n8k16.row.col.f32.bf16.bf16.f32 "
        "{%0,%1,%2,%3}, {%4,%5,%6,%7}, {%8,%9}, {%0,%1,%2,%3};"
        : "+f"(c[0]), "+f"(c[1]), "+f"(c[2]), "+f"(c[3])
        : "r"(a[0]), "r"(a[1]), "r"(a[2]), "r"(a[3]), "r"(b0), "r"(b1));
}
#define LDMX4(r0, r1, r2, r3, addr) \
    asm volatile("ldmatrix.sync.aligned.m8n8.x4.shared.b16 {%0,%1,%2,%3}, [%4];" \
        : "=r"(r0), "=r"(r1), "=r"(r2), "=r"(r3) : "r"(addr))

#define CP_ASYNC16(dst, src) \
    asm volatile("cp.async.cg.shared.global [%0], [%1], 16;" :: "r"(dst), "l"(src) : "memory")
#define CP_COMMIT() asm volatile("cp.async.commit_group;" ::: "memory")

// ---------------------------------------------------------------------------
// Kernel 0: split Wo (fp32) into bf16 hi/lo
// ---------------------------------------------------------------------------
__global__ void __launch_bounds__(256) wo_split_kernel(const float* __restrict__ Wo)
{
    const int i = (blockIdx.x * 256 + threadIdx.x) * 4;
    float4 w = *reinterpret_cast<const float4*>(Wo + i);
    __nv_bfloat16 h0 = __float2bfloat16(w.x), h1 = __float2bfloat16(w.y);
    __nv_bfloat16 h2 = __float2bfloat16(w.z), h3 = __float2bfloat16(w.w);
    uint32_t* oh = reinterpret_cast<uint32_t*>(g_woh + i);
    uint32_t* ol = reinterpret_cast<uint32_t*>(g_wol + i);
    oh[0] = pack2(h0, h1); oh[1] = pack2(h2, h3);
    ol[0] = pack2(__float2bfloat16(w.x - __bfloat162float(h0)),
                  __float2bfloat16(w.y - __bfloat162float(h1)));
    ol[1] = pack2(__float2bfloat16(w.z - __bfloat162float(h2)),
                  __float2bfloat16(w.w - __bfloat162float(h3)));
}

// ---------------------------------------------------------------------------
// Kernel 1: fused QKV projection
// ---------------------------------------------------------------------------
__global__ void __launch_bounds__(256) qkv_proj_kernel(
    const float* __restrict__ queries, const float* __restrict__ keys,
    const float* __restrict__ values,
    const float* __restrict__ Wq, const float* __restrict__ Wk,
    const float* __restrict__ Wv)
{
    __shared__ float Wqs[64][64];
    __shared__ float Wks[64][64];
    __shared__ float Wvs[64][64];
    const int tid = threadIdx.x;
#pragma unroll
    for (int u = 0; u < 4; u++) {
        int idx = tid + u * 256;
        reinterpret_cast<float4*>(Wqs)[idx] = reinterpret_cast<const float4*>(Wq)[idx];
        reinterpret_cast<float4*>(Wks)[idx] = reinterpret_cast<const float4*>(Wk)[idx];
        reinterpret_cast<float4*>(Wvs)[idx] = reinterpret_cast<const float4*>(Wv)[idx];
    }
    __syncthreads();

    const int r  = blockIdx.x * 256 + tid;
    const int bh = r >> 11;
    const int l  = r & 2047;
    const int n  = bh >> 4;
    const int h  = bh & 15;
    const size_t in_off = (size_t)n * LSEQ * EMB + (size_t)l * EMB + (size_t)h * HD;

    {
        float4 xr[16];
#pragma unroll
        for (int i = 0; i < 16; i++) xr[i] = reinterpret_cast<const float4*>(queries + in_off)[i];
        uint32_t* oh = reinterpret_cast<uint32_t*>(g_qh + (size_t)r * HD);
        uint32_t* ol = reinterpret_cast<uint32_t*>(g_ql + (size_t)r * HD);
#pragma unroll 4
        for (int e2 = 0; e2 < 32; e2++) {
            float a0 = 0.f, a1 = 0.f;
            const float4* w0 = reinterpret_cast<const float4*>(Wqs[2*e2]);
            const float4* w1 = reinterpret_cast<const float4*>(Wqs[2*e2+1]);
#pragma unroll
            for (int i = 0; i < 16; i++) {
                float4 x = xr[i], u = w0[i], v = w1[i];
                a0 = fmaf(x.x,u.x,fmaf(x.y,u.y,fmaf(x.z,u.z,fmaf(x.w,u.w,a0))));
                a1 = fmaf(x.x,v.x,fmaf(x.y,v.y,fmaf(x.z,v.z,fmaf(x.w,v.w,a1))));
            }
            a0 *= QS; a1 *= QS;
            __nv_bfloat16 h0 = __float2bfloat16(a0), h1 = __float2bfloat16(a1);
            oh[e2] = pack2(h0, h1);
            ol[e2] = pack2(__float2bfloat16(a0 - __bfloat162float(h0)),
                           __float2bfloat16(a1 - __bfloat162float(h1)));
        }
    }
    {
        float4 xr[16];
#pragma unroll
        for (int i = 0; i < 16; i++) xr[i] = reinterpret_cast<const float4*>(keys + in_off)[i];
        uint32_t* oh = reinterpret_cast<uint32_t*>(g_kh + (size_t)r * HD);
        uint32_t* ol = reinterpret_cast<uint32_t*>(g_kl + (size_t)r * HD);
#pragma unroll 4
        for (int e2 = 0; e2 < 32; e2++) {
            float a0 = 0.f, a1 = 0.f;
            const float4* w0 = reinterpret_cast<const float4*>(Wks[2*e2]);
            const float4* w1 = reinterpret_cast<const float4*>(Wks[2*e2+1]);
#pragma unroll
            for (int i = 0; i < 16; i++) {
                float4 x = xr[i], u = w0[i], v = w1[i];
                a0 = fmaf(x.x,u.x,fmaf(x.y,u.y,fmaf(x.z,u.z,fmaf(x.w,u.w,a0))));
                a1 = fmaf(x.x,v.x,fmaf(x.y,v.y,fmaf(x.z,v.z,fmaf(x.w,v.w,a1))));
            }
            __nv_bfloat16 h0 = __float2bfloat16(a0), h1 = __float2bfloat16(a1);
            oh[e2] = pack2(h0, h1);
            ol[e2] = pack2(__float2bfloat16(a0 - __bfloat162float(h0)),
                           __float2bfloat16(a1 - __bfloat162float(h1)));
        }
    }
    {
        float4 xr[16];
#pragma unroll
        for (int i = 0; i < 16; i++) xr[i] = reinterpret_cast<const float4*>(values + in_off)[i];
        __nv_bfloat16* vh = g_vht + (size_t)bh * HD * LSEQ + l;
        __nv_bfloat16* vl = g_vlt + (size_t)bh * HD * LSEQ + l;
#pragma unroll 4
        for (int e = 0; e < 64; e++) {
            float a0 = 0.f;
            const float4* w0 = reinterpret_cast<const float4*>(Wvs[e]);
#pragma unroll
            for (int i = 0; i < 16; i++) {
                float4 x = xr[i], u = w0[i];
                a0 = fmaf(x.x,u.x,fmaf(x.y,u.y,fmaf(x.z,u.z,fmaf(x.w,u.w,a0))));
            }
            __nv_bfloat16 h0 = __float2bfloat16(a0);
            vh[(size_t)e * LSEQ] = h0;
            vl[(size_t)e * LSEQ] = __float2bfloat16(a0 - __bfloat162float(h0));
        }
    }
}

// ---------------------------------------------------------------------------
// Kernel 2: flash attention. 8 warps x 32 q-rows = 256 rows/block.
// ldmatrix loads; S = 3-pass split, PV = 3-pass (Ph*Vh + Ph*Vl + Pl*Vh).
// ---------------------------------------------------------------------------
#define KSTR    72
#define KSTRB   144
#define BUF_SZ  9216
#define STG_SZ  36864
#define SM_ATT  73728

__global__ void __launch_bounds__(256, 1) attn_kernel()
{
    extern __shared__ char sm[];
    const uint32_t smb = smem_u32(sm);
    const int tid = threadIdx.x, wid = tid >> 5, lane = tid & 31;
    const int g = lane >> 2, t = lane & 3;
    const int bh = blockIdx.y;
    const int q0 = blockIdx.x * 256;
    const int warp_q = q0 + wid * 32;

    const int lm_m = lane >> 3, lm_r = lane & 7;
    const uint32_t lmoff = (uint32_t)((8 * (lm_m >> 1) + lm_r) * KSTRB + (lm_m & 1) * 16);

    // ---- Q fragments: 2 m-tiles x 4 k-steps, hi and lo ----
    uint32_t qh[2][4][4], ql[2][4][4];
    {
        const uint32_t* bhp = reinterpret_cast<const uint32_t*>(g_qh) + ((size_t)bh * LSEQ + warp_q) * 32;
        const uint32_t* blp = reinterpret_cast<const uint32_t*>(g_ql) + ((size_t)bh * LSEQ + warp_q) * 32;
#pragma unroll
        for (int mi = 0; mi < 2; mi++) {
            const int r0 = mi * 16 + g, r1 = r0 + 8;
#pragma unroll
            for (int ks = 0; ks < 4; ks++) {
                qh[mi][ks][0] = bhp[(size_t)r0 * 32 + 8*ks + t];
                qh[mi][ks][1] = bhp[(size_t)r1 * 32 + 8*ks + t];
                qh[mi][ks][2] = bhp[(size_t)r0 * 32 + 8*ks + t + 4];
                qh[mi][ks][3] = bhp[(size_t)r1 * 32 + 8*ks + t + 4];
                ql[mi][ks][0] = blp[(size_t)r0 * 32 + 8*ks + t];
                ql[mi][ks][1] = blp[(size_t)r1 * 32 + 8*ks + t];
                ql[mi][ks][2] = blp[(size_t)r0 * 32 + 8*ks + t + 4];
                ql[mi][ks][3] = blp[(size_t)r1 * 32 + 8*ks + t + 4];
            }
        }
    }

    auto load_stage = [&](int kt, int s) {
        const uint32_t sb = smb + s * STG_SZ;
        const int k0 = kt * 64;
        const __nv_bfloat16* kh = g_kh + ((size_t)bh * LSEQ + k0) * HD;
        const __nv_bfloat16* kl = g_kl + ((size_t)bh * LSEQ + k0) * HD;
        const __nv_bfloat16* vh = g_vht + (size_t)bh * HD * LSEQ + k0;
        const __nv_bfloat16* vl = g_vlt + (size_t)bh * HD * LSEQ + k0;
#pragma unroll
        for (int u = 0; u < 2; u++) {
            int c = tid + u * 256;
            int row = c >> 3, col = c & 7;
            uint32_t dst = sb + row * KSTRB + col * 16;
            CP_ASYNC16(dst,                 kh + (size_t)row * HD + col * 8);
            CP_ASYNC16(dst + BUF_SZ,        kl + (size_t)row * HD + col * 8);
            CP_ASYNC16(dst + 2 * BUF_SZ,    vh + (size_t)row * LSEQ + col * 8);
            CP_ASYNC16(dst + 3 * BUF_SZ,    vl + (size_t)row * LSEQ + col * 8);
        }
    };

    float o[2][8][4];
#pragma unroll
    for (int mi = 0; mi < 2; mi++)
#pragma unroll
        for (int i = 0; i < 8; i++)
#pragma unroll
            for (int j = 0; j < 4; j++) o[mi][i][j] = 0.f;
    float ls[2][2] = {};

    load_stage(0, 0); CP_COMMIT();

    for (int kt = 0; kt < 32; kt++) {
        const int s = kt & 1;
        if (kt < 31) {
            load_stage(kt + 1, s ^ 1); CP_COMMIT();
            asm volatile("cp.async.wait_group 1;" ::: "memory");
        } else {
            asm volatile("cp.async.wait_group 0;" ::: "memory");
        }
        __syncthreads();

        const uint32_t KHb = smb + s * STG_SZ;
        const uint32_t KLb = KHb + BUF_SZ;
        const uint32_t VHb = KHb + 2 * BUF_SZ;
        const uint32_t VLb = KHb + 3 * BUF_SZ;

#pragma unroll
        for (int half = 0; half < 2; half++) {
            const uint32_t hoff = half * 32 * KSTRB;   // 32 key rows

            // ---- S (3-pass) over 32 keys ----
            float sc[2][4][4];
#pragma unroll
            for (int mi = 0; mi < 2; mi++)
#pragma unroll
                for (int nt = 0; nt < 4; nt++)
#pragma unroll
                    for (int j = 0; j < 4; j++) sc[mi][nt][j] = 0.f;

#pragma unroll
            for (int ks = 0; ks < 4; ks++) {
                uint32_t kf[8], lf[8];
                LDMX4(kf[0], kf[1], kf[2], kf[3], KHb + hoff + ks * 32 + lmoff);
                LDMX4(kf[4], kf[5], kf[6], kf[7], KHb + hoff + 16 * KSTRB + ks * 32 + lmoff);
                LDMX4(lf[0], lf[1], lf[2], lf[3], KLb + hoff + ks * 32 + lmoff);
                LDMX4(lf[4], lf[5], lf[6], lf[7], KLb + hoff + 16 * KSTRB + ks * 32 + lmoff);
#pragma unroll
                for (int mi = 0; mi < 2; mi++)
#pragma unroll
                    for (int nt = 0; nt < 4; nt++) {
                        mma16816(sc[mi][nt], qh[mi][ks], kf[2*nt], kf[2*nt+1]);
                        mma16816(sc[mi][nt], qh[mi][ks], lf[2*nt], lf[2*nt+1]);
                        mma16816(sc[mi][nt], ql[mi][ks], kf[2*nt], kf[2*nt+1]);
                    }
            }

            // ---- softmax: exp2, lsum, P hi/lo fragments ----
            uint32_t ph[2][2][4], pl[2][2][4];
#pragma unroll
            for (int mi = 0; mi < 2; mi++)
#pragma unroll
                for (int nt = 0; nt < 4; nt++) {
                    float p0 = ex2f(sc[mi][nt][0]);
                    float p1 = ex2f(sc[mi][nt][1]);
                    float p2 = ex2f(sc[mi][nt][2]);
                    float p3 = ex2f(sc[mi][nt][3]);
                    ls[mi][0] += p0 + p1;
                    ls[mi][1] += p2 + p3;
                    __nv_bfloat16 h0 = __float2bfloat16(p0), h1 = __float2bfloat16(p1);
                    __nv_bfloat16 h2 = __float2bfloat16(p2), h3 = __float2bfloat16(p3);
                    const int kc = nt >> 1, su = (nt & 1) * 2;
                    ph[mi][kc][su + 0] = pack2(h0, h1);
                    ph[mi][kc][su + 1] = pack2(h2, h3);
                    pl[mi][kc][su + 0] = pack2(__float2bfloat16(p0 - __bfloat162float(h0)),
                                               __float2bfloat16(p1 - __bfloat162float(h1)));
                    pl[mi][kc][su + 1] = pack2(__float2bfloat16(p2 - __bfloat162float(h2)),
                                               __float2bfloat16(p3 - __bfloat162float(h3)));
                }

            // ---- PV (3-pass): O += Ph*Vh + Ph*Vl + Pl*Vh ----
            const uint32_t koff = half * 64;
#pragma unroll
            for (int kc = 0; kc < 2; kc++) {
                const uint32_t kb = koff + kc * 32;
#pragma unroll
                for (int a = 0; a < 8; a += 2) {
                    uint32_t vh[4], vl[4];
                    LDMX4(vh[0], vh[1], vh[2], vh[3], VHb + a * 8 * KSTRB + kb + lmoff);
                    LDMX4(vl[0], vl[1], vl[2], vl[3], VLb + a * 8 * KSTRB + kb + lmoff);
#pragma unroll
                    for (int mi = 0; mi < 2; mi++) {
                        mma16816(o[mi][a],     ph[mi][kc], vh[0], vh[1]);
                        mma16816(o[mi][a],     ph[mi][kc], vl[0], vl[1]);
                        mma16816(o[mi][a],     pl[mi][kc], vh[0], vh[1]);
                        mma16816(o[mi][a + 1], ph[mi][kc], vh[2], vh[3]);
                        mma16816(o[mi][a + 1], ph[mi][kc], vl[2], vl[3]);
                        mma16816(o[mi][a + 1], pl[mi][kc], vh[2], vh[3]);
                    }
                }
            }
        }
        __syncthreads();
    }

    // ---- epilogue: normalize, split hi/lo bf16, write token-major ----
#pragma unroll
    for (int mi = 0; mi < 2; mi++) {
        ls[mi][0] += __shfl_xor_sync(0xffffffffu, ls[mi][0], 1);
        ls[mi][0] += __shfl_xor_sync(0xffffffffu, ls[mi][0], 2);
        ls[mi][1] += __shfl_xor_sync(0xffffffffu, ls[mi][1], 1);
        ls[mi][1] += __shfl_xor_sync(0xffffffffu, ls[mi][1], 2);
    }

    const int n = bh >> 4, h = bh & 15;
#pragma unroll
    for (int mi = 0; mi < 2; mi++) {
        const float inv0 = 1.f / ls[mi][0], inv1 = 1.f / ls[mi][1];
        const int r1 = warp_q + 16 * mi + g, r2 = r1 + 8;
        const size_t b1 = ((size_t)n * LSEQ + r1) * EMB + h * HD;
        const size_t b2 = ((size_t)n * LSEQ + r2) * EMB + h * HD;
#pragma unroll
        for (int nd = 0; nd < 8; nd++) {
            const int dcol = 8 * nd + 2 * t;
            float v0 = o[mi][nd][0] * inv0, v1 = o[mi][nd][1] * inv0;
            float v2 = o[mi][nd][2] * inv1, v3 = o[mi][nd][3] * inv1;
            __nv_bfloat16 h0 = __float2bfloat16(v0), h1 = __float2bfloat16(v1);
            __nv_bfloat16 h2 = __float2bfloat16(v2), h3 = __float2bfloat16(v3);
            *reinterpret_cast<uint32_t*>(g_aoh + b1 + dcol) = pack2(h0, h1);
            *reinterpret_cast<uint32_t*>(g_aol + b1 + dcol) =
                pack2(__float2bfloat16(v0 - __bfloat162float(h0)),
                      __float2bfloat16(v1 - __bfloat162float(h1)));
            *reinterpret_cast<uint32_t*>(g_aoh + b2 + dcol) = pack2(h2, h3);
            *reinterpret_cast<uint32_t*>(g_aol + b2 + dcol) =
                pack2(__float2bfloat16(v2 - __bfloat162float(h2)),
                      __float2bfloat16(v3 - __bfloat162float(h3)));
        }
    }
}

// ---------------------------------------------------------------------------
// Kernel 3: output projection on HMMA, 3-stage cp.async pipeline.
// ---------------------------------------------------------------------------
#define OSTRB 80
#define OBUF  10240
#define OSTG  40960
#define SM_GEMM 122880     // 3 stages

__global__ void __launch_bounds__(256, 1) out_proj_kernel(
    const float* __restrict__ bias, float* __restrict__ C)
{
    extern __shared__ char sm[];
    const uint32_t smb = smem_u32(sm);
    const int tid = threadIdx.x, wid = tid >> 5, lane = tid & 31;
    const int g = lane >> 2, t = lane & 3;
    const int m0 = blockIdx.y * 128;
    const int n0 = blockIdx.x * 128;
    const int wm = (wid & 3) * 32;
    const int wn = (wid >> 2) * 64;

    auto load_stage = [&](int kt, int s) {
        const uint32_t sb = smb + s * OSTG;
        const int k0 = kt * 32;
        const __nv_bfloat16* ah = g_aoh + (size_t)m0 * EMB + k0;
        const __nv_bfloat16* al = g_aol + (size_t)m0 * EMB + k0;
        const __nv_bfloat16* bhp = g_woh + (size_t)n0 * EMB + k0;
        const __nv_bfloat16* blp = g_wol + (size_t)n0 * EMB + k0;
#pragma unroll
        for (int u = 0; u < 2; u++) {
            int c = tid + u * 256;
            int row = c >> 2, col = c & 3;
            uint32_t dst = sb + row * OSTRB + col * 16;
            const size_t so = (size_t)row * EMB + col * 8;
            CP_ASYNC16(dst,            ah + so);
            CP_ASYNC16(dst + OBUF,     al + so);
            CP_ASYNC16(dst + 2*OBUF,   bhp + so);
            CP_ASYNC16(dst + 3*OBUF,   blp + so);
        }
    };

    float acc[2][8][4];
#pragma unroll
    for (int i = 0; i < 2; i++)
#pragma unroll
        for (int j = 0; j < 8; j++)
#pragma unroll
            for (int k = 0; k < 4; k++) acc[i][j][k] = 0.f;

    load_stage(0, 0); CP_COMMIT();
    load_stage(1, 1); CP_COMMIT();

    for (int kt = 0; kt < 32; kt++) {
        const int s = kt % 3;
        if (kt < 30) {
            load_stage(kt + 2, (kt + 2) % 3); CP_COMMIT();
            asm volatile("cp.async.wait_group 2;" ::: "memory");
        } else {
            asm volatile("cp.async.wait_group 0;" ::: "memory");
        }
        __syncthreads();

        const uint32_t AHo = s * OSTG;
        const uint32_t ALo = AHo + OBUF;
        const uint32_t BHo = AHo + 2 * OBUF;
        const uint32_t BLo = AHo + 3 * OBUF;

#pragma unroll
        for (int ks = 0; ks < 2; ks++) {
            uint32_t ah[2][4], al[2][4];
#pragma unroll
            for (int mi = 0; mi < 2; mi++) {
                const uint32_t rb = (wm + mi * 16 + g) * OSTRB + ks * 32 + t * 4;
                ah[mi][0] = *reinterpret_cast<const uint32_t*>(sm + AHo + rb);
                ah[mi][1] = *reinterpret_cast<const uint32_t*>(sm + AHo + rb + 8 * OSTRB);
                ah[mi][2] = *reinterpret_cast<const uint32_t*>(sm + AHo + rb + 16);
                ah[mi][3] = *reinterpret_cast<const uint32_t*>(sm + AHo + rb + 8 * OSTRB + 16);
                al[mi][0] = *reinterpret_cast<const uint32_t*>(sm + ALo + rb);
                al[mi][1] = *reinterpret_cast<const uint32_t*>(sm + ALo + rb + 8 * OSTRB);
                al[mi][2] = *reinterpret_cast<const uint32_t*>(sm + ALo + rb + 16);
                al[mi][3] = *reinterpret_cast<const uint32_t*>(sm + ALo + rb + 8 * OSTRB + 16);
            }
#pragma unroll
            for (int ni = 0; ni < 8; ni++) {
                const uint32_t rb = (wn + ni * 8 + g) * OSTRB + ks * 32 + t * 4;
                uint32_t bh0 = *reinterpret_cast<const uint32_t*>(sm + BHo + rb);
                uint32_t bh1 = *reinterpret_cast<const uint32_t*>(sm + BHo + rb + 16);
                uint32_t bl0 = *reinterpret_cast<const uint32_t*>(sm + BLo + rb);
                uint32_t bl1 = *reinterpret_cast<const uint32_t*>(sm + BLo + rb + 16);
#pragma unroll
                for (int mi = 0; mi < 2; mi++) {
                    mma16816(acc[mi][ni], ah[mi], bh0, bh1);
                    mma16816(acc[mi][ni], ah[mi], bl0, bl1);
                    mma16816(acc[mi][ni], al[mi], bh0, bh1);
                }
            }
        }
        __syncthreads();
    }

#pragma unroll
    for (int mi = 0; mi < 2; mi++) {
        const int r1 = m0 + wm + mi * 16 + g;
        const int r2 = r1 + 8;
#pragma unroll
        for (int ni = 0; ni < 8; ni++) {
            const int col = n0 + wn + ni * 8 + 2 * t;
            float2 bv = *reinterpret_cast<const float2*>(bias + col);
            *reinterpret_cast<float2*>(C + (size_t)r1 * EMB + col) =
                make_float2(acc[mi][ni][0] + bv.x, acc[mi][ni][1] + bv.y);
            *reinterpret_cast<float2*>(C + (size_t)r2 * EMB + col) =
                make_float2(acc[mi][ni][2] + bv.x, acc[mi][ni][3] + bv.y);
        }
    }
}

// ---------------------------------------------------------------------------
extern "C" void kernel_launch(void* const* d_in, const int* in_sizes, int n_in,
                              void* d_out, int out_size)
{
    const float* values  = (const float*)d_in[0];
    const float* keys    = (const float*)d_in[1];
    const float* queries = (const float*)d_in[2];
    const float* Wv      = (const float*)d_in[3];
    const float* Wk      = (const float*)d_in[4];
    const float* Wq      = (const float*)d_in[5];
    const float* Wo      = (const float*)d_in[6];
    const float* bo      = (const float*)d_in[7];
    float* out = (float*)d_out;

    static bool attr_set = false;
    if (!attr_set) {
        cudaFuncSetAttribute(attn_kernel,
                             cudaFuncAttributeMaxDynamicSharedMemorySize, SM_ATT);
        cudaFuncSetAttribute(out_proj_kernel,
                             cudaFuncAttributeMaxDynamicSharedMemorySize, SM_GEMM);
        attr_set = true;
    }

    wo_split_kernel<<<EMB * EMB / 1024, 256>>>(Wo);
    qkv_proj_kernel<<<(BHN * LSEQ) / 256, 256>>>(queries, keys, values, Wq, Wk, Wv);

    dim3 g2(LSEQ / 256, BHN);
    attn_kernel<<<g2, 256, SM_ATT>>>();

    dim3 g3(EMB / 128, (NB * LSEQ) / 128);
    out_proj_kernel<<<g3, 256, SM_GEMM>>>(bo, out);
}

// round 7
// speedup vs baseline: 1.0733x; 1.0733x over previous
#include <cuda_runtime.h>
#include <cuda_bf16.h>
#include <math.h>
#include <stdint.h>

#define NB   4
#define LSEQ 2048
#define EMB  1024
#define NH   16
#define HD   64
#define BHN  (NB*NH)
// Q pre-scale: (1/sqrt(EMB)) * log2(e)  -> scores come out in log2 domain
#define QS   (0.04508422f)

// ---------------- scratch ----------------
__device__ __nv_bfloat16 g_qh[BHN*LSEQ*HD];   // [bh][l][d]  (pre-scaled)
__device__ __nv_bfloat16 g_ql[BHN*LSEQ*HD];
__device__ __nv_bfloat16 g_kh[BHN*LSEQ*HD];
__device__ __nv_bfloat16 g_kl[BHN*LSEQ*HD];
__device__ __nv_bfloat16 g_vh[BHN*LSEQ*HD];   // row-major [bh][l][d] (trans at use)
__device__ __nv_bfloat16 g_vl[BHN*LSEQ*HD];
__device__ __nv_bfloat16 g_aoh[NB*LSEQ*EMB];  // attention out hi  [token][E]
__device__ __nv_bfloat16 g_aol[NB*LSEQ*EMB];  // attention out lo
__device__ __nv_bfloat16 g_woh[EMB*EMB];      // Wo hi  [e][k]
__device__ __nv_bfloat16 g_wol[EMB*EMB];      // Wo lo

__device__ __forceinline__ uint32_t pack2(__nv_bfloat16 a, __nv_bfloat16 b) {
    return (uint32_t)__bfloat16_as_ushort(a) | ((uint32_t)__bfloat16_as_ushort(b) << 16);
}
__device__ __forceinline__ uint32_t smem_u32(const void* p) {
    uint32_t a;
    asm("{ .reg .u64 t; cvta.to.shared.u64 t, %1; cvt.u32.u64 %0, t; }" : "=r"(a) : "l"(p));
    return a;
}
__device__ __forceinline__ float ex2f(float x) {
    float y; asm("ex2.approx.f32 %0, %1;" : "=f"(y) : "f"(x)); return y;
}
__device__ __forceinline__ void mma16816(float* c, const uint32_t* a,
                                         uint32_t b0, uint32_t b1) {
    asm volatile("mma.sync.aligned.m16n8k16.row.col.f32.bf16.bf16.f32 "
        "{%0,%1,%2,%3}, {%4,%5,%6,%7}, {%8,%9}, {%0,%1,%2,%3};"
        : "+f"(c[0]), "+f"(c[1]), "+f"(c[2]), "+f"(c[3])
        : "r"(a[0]), "r"(a[1]), "r"(a[2]), "r"(a[3]), "r"(b0), "r"(b1));
}
#define LDMX4(r0, r1, r2, r3, addr) \
    asm volatile("ldmatrix.sync.aligned.m8n8.x4.shared.b16 {%0,%1,%2,%3}, [%4];" \
        : "=r"(r0), "=r"(r1), "=r"(r2), "=r"(r3) : "r"(addr))
#define LDMX4T(r0, r1, r2, r3, addr) \
    asm volatile("ldmatrix.sync.aligned.m8n8.x4.trans.shared.b16 {%0,%1,%2,%3}, [%4];" \
        : "=r"(r0), "=r"(r1), "=r"(r2), "=r"(r3) : "r"(addr))

#define CP_ASYNC16(dst, src) \
    asm volatile("cp.async.cg.shared.global [%0], [%1], 16;" :: "r"(dst), "l"(src) : "memory")
#define CP_COMMIT() asm volatile("cp.async.commit_group;" ::: "memory")

// ---------------------------------------------------------------------------
// Kernel 0: split Wo (fp32) into bf16 hi/lo
// ---------------------------------------------------------------------------
__global__ void __launch_bounds__(256) wo_split_kernel(const float* __restrict__ Wo)
{
    const int i = (blockIdx.x * 256 + threadIdx.x) * 4;
    float4 w = *reinterpret_cast<const float4*>(Wo + i);
    __nv_bfloat16 h0 = __float2bfloat16(w.x), h1 = __float2bfloat16(w.y);
    __nv_bfloat16 h2 = __float2bfloat16(w.z), h3 = __float2bfloat16(w.w);
    uint32_t* oh = reinterpret_cast<uint32_t*>(g_woh + i);
    uint32_t* ol = reinterpret_cast<uint32_t*>(g_wol + i);
    oh[0] = pack2(h0, h1); oh[1] = pack2(h2, h3);
    ol[0] = pack2(__float2bfloat16(w.x - __bfloat162float(h0)),
                  __float2bfloat16(w.y - __bfloat162float(h1)));
    ol[1] = pack2(__float2bfloat16(w.z - __bfloat162float(h2)),
                  __float2bfloat16(w.w - __bfloat162float(h3)));
}

// ---------------------------------------------------------------------------
// Kernel 1: fused QKV projection. All outputs row-major coalesced now.
// ---------------------------------------------------------------------------
__global__ void __launch_bounds__(256) qkv_proj_kernel(
    const float* __restrict__ queries, const float* __restrict__ keys,
    const float* __restrict__ values,
    const float* __restrict__ Wq, const float* __restrict__ Wk,
    const float* __restrict__ Wv)
{
    __shared__ float Wqs[64][64];
    __shared__ float Wks[64][64];
    __shared__ float Wvs[64][64];
    const int tid = threadIdx.x;
#pragma unroll
    for (int u = 0; u < 4; u++) {
        int idx = tid + u * 256;
        reinterpret_cast<float4*>(Wqs)[idx] = reinterpret_cast<const float4*>(Wq)[idx];
        reinterpret_cast<float4*>(Wks)[idx] = reinterpret_cast<const float4*>(Wk)[idx];
        reinterpret_cast<float4*>(Wvs)[idx] = reinterpret_cast<const float4*>(Wv)[idx];
    }
    __syncthreads();

    const int r  = blockIdx.x * 256 + tid;
    const int bh = r >> 11;
    const int l  = r & 2047;
    const int n  = bh >> 4;
    const int h  = bh & 15;
    const size_t in_off = (size_t)n * LSEQ * EMB + (size_t)l * EMB + (size_t)h * HD;

    {
        float4 xr[16];
#pragma unroll
        for (int i = 0; i < 16; i++) xr[i] = reinterpret_cast<const float4*>(queries + in_off)[i];
        uint32_t* oh = reinterpret_cast<uint32_t*>(g_qh + (size_t)r * HD);
        uint32_t* ol = reinterpret_cast<uint32_t*>(g_ql + (size_t)r * HD);
#pragma unroll 4
        for (int e2 = 0; e2 < 32; e2++) {
            float a0 = 0.f, a1 = 0.f;
            const float4* w0 = reinterpret_cast<const float4*>(Wqs[2*e2]);
            const float4* w1 = reinterpret_cast<const float4*>(Wqs[2*e2+1]);
#pragma unroll
            for (int i = 0; i < 16; i++) {
                float4 x = xr[i], u = w0[i], v = w1[i];
                a0 = fmaf(x.x,u.x,fmaf(x.y,u.y,fmaf(x.z,u.z,fmaf(x.w,u.w,a0))));
                a1 = fmaf(x.x,v.x,fmaf(x.y,v.y,fmaf(x.z,v.z,fmaf(x.w,v.w,a1))));
            }
            a0 *= QS; a1 *= QS;
            __nv_bfloat16 h0 = __float2bfloat16(a0), h1 = __float2bfloat16(a1);
            oh[e2] = pack2(h0, h1);
            ol[e2] = pack2(__float2bfloat16(a0 - __bfloat162float(h0)),
                           __float2bfloat16(a1 - __bfloat162float(h1)));
        }
    }
    {
        float4 xr[16];
#pragma unroll
        for (int i = 0; i < 16; i++) xr[i] = reinterpret_cast<const float4*>(keys + in_off)[i];
        uint32_t* oh = reinterpret_cast<uint32_t*>(g_kh + (size_t)r * HD);
        uint32_t* ol = reinterpret_cast<uint32_t*>(g_kl + (size_t)r * HD);
#pragma unroll 4
        for (int e2 = 0; e2 < 32; e2++) {
            float a0 = 0.f, a1 = 0.f;
            const float4* w0 = reinterpret_cast<const float4*>(Wks[2*e2]);
            const float4* w1 = reinterpret_cast<const float4*>(Wks[2*e2+1]);
#pragma unroll
            for (int i = 0; i < 16; i++) {
                float4 x = xr[i], u = w0[i], v = w1[i];
                a0 = fmaf(x.x,u.x,fmaf(x.y,u.y,fmaf(x.z,u.z,fmaf(x.w,u.w,a0))));
                a1 = fmaf(x.x,v.x,fmaf(x.y,v.y,fmaf(x.z,v.z,fmaf(x.w,v.w,a1))));
            }
            __nv_bfloat16 h0 = __float2bfloat16(a0), h1 = __float2bfloat16(a1);
            oh[e2] = pack2(h0, h1);
            ol[e2] = pack2(__float2bfloat16(a0 - __bfloat162float(h0)),
                           __float2bfloat16(a1 - __bfloat162float(h1)));
        }
    }
    {
        float4 xr[16];
#pragma unroll
        for (int i = 0; i < 16; i++) xr[i] = reinterpret_cast<const float4*>(values + in_off)[i];
        uint32_t* oh = reinterpret_cast<uint32_t*>(g_vh + (size_t)r * HD);
        uint32_t* ol = reinterpret_cast<uint32_t*>(g_vl + (size_t)r * HD);
#pragma unroll 4
        for (int e2 = 0; e2 < 32; e2++) {
            float a0 = 0.f, a1 = 0.f;
            const float4* w0 = reinterpret_cast<const float4*>(Wvs[2*e2]);
            const float4* w1 = reinterpret_cast<const float4*>(Wvs[2*e2+1]);
#pragma unroll
            for (int i = 0; i < 16; i++) {
                float4 x = xr[i], u = w0[i], v = w1[i];
                a0 = fmaf(x.x,u.x,fmaf(x.y,u.y,fmaf(x.z,u.z,fmaf(x.w,u.w,a0))));
                a1 = fmaf(x.x,v.x,fmaf(x.y,v.y,fmaf(x.z,v.z,fmaf(x.w,v.w,a1))));
            }
            __nv_bfloat16 h0 = __float2bfloat16(a0), h1 = __float2bfloat16(a1);
            oh[e2] = pack2(h0, h1);
            ol[e2] = pack2(__float2bfloat16(a0 - __bfloat162float(h0)),
                           __float2bfloat16(a1 - __bfloat162float(h1)));
        }
    }
}

// ---------------------------------------------------------------------------
// Kernel 2: flash attention. 8 warps x 16 q-rows = 128 rows/block, 2 CTAs/SM.
// K via ldmatrix, V row-major via ldmatrix.trans. 3-pass S, 3-pass PV.
// ---------------------------------------------------------------------------
#define KSTRB   144
#define BUF_SZ  9216
#define STG_SZ  36864
#define SM_ATT  73728

__global__ void __launch_bounds__(256, 2) attn_kernel()
{
    extern __shared__ char sm[];
    const uint32_t smb = smem_u32(sm);
    const int tid = threadIdx.x, wid = tid >> 5, lane = tid & 31;
    const int g = lane >> 2, t = lane & 3;
    const int bh = blockIdx.y;
    const int q0 = blockIdx.x * 128;
    const int warp_q = q0 + wid * 16;

    // K (no-trans) lane offset: tiles = {rows0-7+0B, rows0-7+16B, rows8-15+0B, rows8-15+16B}
    const int lm = lane >> 3, lr = lane & 7;
    const uint32_t koffm = (uint32_t)((8 * (lm >> 1) + lr) * KSTRB + (lm & 1) * 16);
    // V (trans) lane offset: tiles = {keys0-7 d+0, keys8-15 d+0, keys0-7 d+8, keys8-15 d+8}
    const uint32_t voffm = (uint32_t)(((lm & 1) * 8 + lr) * KSTRB + (lm >> 1) * 16);

    // ---- Q fragments (hi/lo) in registers ----
    uint32_t qh[4][4], ql[4][4];
    {
        const uint32_t* bhp = reinterpret_cast<const uint32_t*>(g_qh) + ((size_t)bh * LSEQ + warp_q) * 32;
        const uint32_t* blp = reinterpret_cast<const uint32_t*>(g_ql) + ((size_t)bh * LSEQ + warp_q) * 32;
#pragma unroll
        for (int ks = 0; ks < 4; ks++) {
            qh[ks][0] = bhp[(size_t)g * 32 + 8*ks + t];
            qh[ks][1] = bhp[(size_t)(g+8) * 32 + 8*ks + t];
            qh[ks][2] = bhp[(size_t)g * 32 + 8*ks + t + 4];
            qh[ks][3] = bhp[(size_t)(g+8) * 32 + 8*ks + t + 4];
            ql[ks][0] = blp[(size_t)g * 32 + 8*ks + t];
            ql[ks][1] = blp[(size_t)(g+8) * 32 + 8*ks + t];
            ql[ks][2] = blp[(size_t)g * 32 + 8*ks + t + 4];
            ql[ks][3] = blp[(size_t)(g+8) * 32 + 8*ks + t + 4];
        }
    }

    auto load_stage = [&](int kt, int s) {
        const uint32_t sb = smb + s * STG_SZ;
        const int k0 = kt * 64;
        const __nv_bfloat16* kh = g_kh + ((size_t)bh * LSEQ + k0) * HD;
        const __nv_bfloat16* kl = g_kl + ((size_t)bh * LSEQ + k0) * HD;
        const __nv_bfloat16* vh = g_vh + ((size_t)bh * LSEQ + k0) * HD;
        const __nv_bfloat16* vl = g_vl + ((size_t)bh * LSEQ + k0) * HD;
#pragma unroll
        for (int u = 0; u < 2; u++) {
            int c = tid + u * 256;
            int row = c >> 3, col = c & 7;
            uint32_t dst = sb + row * KSTRB + col * 16;
            const size_t so = (size_t)row * HD + col * 8;
            CP_ASYNC16(dst,              kh + so);
            CP_ASYNC16(dst + BUF_SZ,     kl + so);
            CP_ASYNC16(dst + 2 * BUF_SZ, vh + so);
            CP_ASYNC16(dst + 3 * BUF_SZ, vl + so);
        }
    };

    float o[8][4];
#pragma unroll
    for (int i = 0; i < 8; i++)
#pragma unroll
        for (int j = 0; j < 4; j++) o[i][j] = 0.f;
    float ls0 = 0.f, ls1 = 0.f;

    load_stage(0, 0); CP_COMMIT();

    for (int kt = 0; kt < 32; kt++) {
        const int s = kt & 1;
        if (kt < 31) {
            load_stage(kt + 1, s ^ 1); CP_COMMIT();
            asm volatile("cp.async.wait_group 1;" ::: "memory");
        } else {
            asm volatile("cp.async.wait_group 0;" ::: "memory");
        }
        __syncthreads();

        const uint32_t KHb = smb + s * STG_SZ;
        const uint32_t KLb = KHb + BUF_SZ;
        const uint32_t VHb = KHb + 2 * BUF_SZ;
        const uint32_t VLb = KHb + 3 * BUF_SZ;

#pragma unroll
        for (int half = 0; half < 2; half++) {
            const uint32_t hoff = half * 32 * KSTRB;   // 32 key rows

            // ---- S (3-pass) over 32 keys: sc[nt][4], nt = 4 n8-tiles ----
            float sc[4][4];
#pragma unroll
            for (int nt = 0; nt < 4; nt++)
#pragma unroll
                for (int j = 0; j < 4; j++) sc[nt][j] = 0.f;

#pragma unroll
            for (int ks = 0; ks < 4; ks++) {
                uint32_t kf[8], lf[8];
                LDMX4(kf[0], kf[1], kf[2], kf[3], KHb + hoff + ks * 32 + koffm);
                LDMX4(kf[4], kf[5], kf[6], kf[7], KHb + hoff + 16 * KSTRB + ks * 32 + koffm);
                LDMX4(lf[0], lf[1], lf[2], lf[3], KLb + hoff + ks * 32 + koffm);
                LDMX4(lf[4], lf[5], lf[6], lf[7], KLb + hoff + 16 * KSTRB + ks * 32 + koffm);
#pragma unroll
                for (int nt = 0; nt < 4; nt++) {
                    mma16816(sc[nt], qh[ks], kf[2*nt], kf[2*nt+1]);
                    mma16816(sc[nt], qh[ks], lf[2*nt], lf[2*nt+1]);
                    mma16816(sc[nt], ql[ks], kf[2*nt], kf[2*nt+1]);
                }
            }

            // ---- softmax: exp2, lsum, P hi/lo A-fragments ----
            uint32_t ph[2][4], pl[2][4];
#pragma unroll
            for (int nt = 0; nt < 4; nt++) {
                float p0 = ex2f(sc[nt][0]);
                float p1 = ex2f(sc[nt][1]);
                float p2 = ex2f(sc[nt][2]);
                float p3 = ex2f(sc[nt][3]);
                ls0 += p0 + p1;
                ls1 += p2 + p3;
                __nv_bfloat16 h0 = __float2bfloat16(p0), h1 = __float2bfloat16(p1);
                __nv_bfloat16 h2 = __float2bfloat16(p2), h3 = __float2bfloat16(p3);
                const int kc = nt >> 1, su = (nt & 1) * 2;
                ph[kc][su + 0] = pack2(h0, h1);
                ph[kc][su + 1] = pack2(h2, h3);
                pl[kc][su + 0] = pack2(__float2bfloat16(p0 - __bfloat162float(h0)),
                                       __float2bfloat16(p1 - __bfloat162float(h1)));
                pl[kc][su + 1] = pack2(__float2bfloat16(p2 - __bfloat162float(h2)),
                                       __float2bfloat16(p3 - __bfloat162float(h3)));
            }

            // ---- PV (3-pass): O += Ph*Vh + Ph*Vl + Pl*Vh, V^T via ldmatrix.trans ----
#pragma unroll
            for (int kc = 0; kc < 2; kc++) {
                const uint32_t kb = hoff + kc * 16 * KSTRB;
#pragma unroll
                for (int db = 0; db < 4; db++) {
                    uint32_t vhf[4], vlf[4];
                    LDMX4T(vhf[0], vhf[1], vhf[2], vhf[3], VHb + kb + db * 32 + voffm);
                    LDMX4T(vlf[0], vlf[1], vlf[2], vlf[3], VLb + kb + db * 32 + voffm);
                    mma16816(o[2*db],     ph[kc], vhf[0], vhf[1]);
                    mma16816(o[2*db],     ph[kc], vlf[0], vlf[1]);
                    mma16816(o[2*db],     pl[kc], vhf[0], vhf[1]);
                    mma16816(o[2*db+1],   ph[kc], vhf[2], vhf[3]);
                    mma16816(o[2*db+1],   ph[kc], vlf[2], vlf[3]);
                    mma16816(o[2*db+1],   pl[kc], vhf[2], vhf[3]);
                }
            }
        }
        __syncthreads();
    }

    // ---- epilogue: normalize, split hi/lo bf16, write token-major ----
    ls0 += __shfl_xor_sync(0xffffffffu, ls0, 1);
    ls0 += __shfl_xor_sync(0xffffffffu, ls0, 2);
    ls1 += __shfl_xor_sync(0xffffffffu, ls1, 1);
    ls1 += __shfl_xor_sync(0xffffffffu, ls1, 2);
    const float inv0 = 1.f / ls0, inv1 = 1.f / ls1;

    const int n = bh >> 4, h = bh & 15;
    const int r1 = warp_q + g, r2 = r1 + 8;
    const size_t b1 = ((size_t)n * LSEQ + r1) * EMB + h * HD;
    const size_t b2 = ((size_t)n * LSEQ + r2) * EMB + h * HD;
#pragma unroll
    for (int nd = 0; nd < 8; nd++) {
        const int dcol = 8 * nd + 2 * t;
        float v0 = o[nd][0] * inv0, v1 = o[nd][1] * inv0;
        float v2 = o[nd][2] * inv1, v3 = o[nd][3] * inv1;
        __nv_bfloat16 h0 = __float2bfloat16(v0), h1 = __float2bfloat16(v1);
        __nv_bfloat16 h2 = __float2bfloat16(v2), h3 = __float2bfloat16(v3);
        *reinterpret_cast<uint32_t*>(g_aoh + b1 + dcol) = pack2(h0, h1);
        *reinterpret_cast<uint32_t*>(g_aol + b1 + dcol) =
            pack2(__float2bfloat16(v0 - __bfloat162float(h0)),
                  __float2bfloat16(v1 - __bfloat162float(h1)));
        *reinterpret_cast<uint32_t*>(g_aoh + b2 + dcol) = pack2(h2, h3);
        *reinterpret_cast<uint32_t*>(g_aol + b2 + dcol) =
            pack2(__float2bfloat16(v2 - __bfloat162float(h2)),
                  __float2bfloat16(v3 - __bfloat162float(h3)));
    }
}

// ---------------------------------------------------------------------------
// Kernel 3: output projection on HMMA, 2-stage, 2 CTAs/SM.
// ---------------------------------------------------------------------------
#define OSTRB 80
#define OBUF  10240
#define OSTG  40960
#define SM_GEMM 81920      // 2 stages

__global__ void __launch_bounds__(256, 2) out_proj_kernel(
    const float* __restrict__ bias, float* __restrict__ C)
{
    extern __shared__ char sm[];
    const uint32_t smb = smem_u32(sm);
    const int tid = threadIdx.x, wid = tid >> 5, lane = tid & 31;
    const int g = lane >> 2, t = lane & 3;
    const int m0 = blockIdx.y * 128;
    const int n0 = blockIdx.x * 128;
    const int wm = (wid & 3) * 32;
    const int wn = (wid >> 2) * 64;

    auto load_stage = [&](int kt, int s) {
        const uint32_t sb = smb + s * OSTG;
        const int k0 = kt * 32;
        const __nv_bfloat16* ah = g_aoh + (size_t)m0 * EMB + k0;
        const __nv_bfloat16* al = g_aol + (size_t)m0 * EMB + k0;
        const __nv_bfloat16* bhp = g_woh + (size_t)n0 * EMB + k0;
        const __nv_bfloat16* blp = g_wol + (size_t)n0 * EMB + k0;
#pragma unroll
        for (int u = 0; u < 2; u++) {
            int c = tid + u * 256;
            int row = c >> 2, col = c & 3;
            uint32_t dst = sb + row * OSTRB + col * 16;
            const size_t so = (size_t)row * EMB + col * 8;
            CP_ASYNC16(dst,            ah + so);
            CP_ASYNC16(dst + OBUF,     al + so);
            CP_ASYNC16(dst + 2*OBUF,   bhp + so);
            CP_ASYNC16(dst + 3*OBUF,   blp + so);
        }
    };

    float acc[2][8][4];
#pragma unroll
    for (int i = 0; i < 2; i++)
#pragma unroll
        for (int j = 0; j < 8; j++)
#pragma unroll
            for (int k = 0; k < 4; k++) acc[i][j][k] = 0.f;

    load_stage(0, 0); CP_COMMIT();

    for (int kt = 0; kt < 32; kt++) {
        const int s = kt & 1;
        if (kt < 31) {
            load_stage(kt + 1, s ^ 1); CP_COMMIT();
            asm volatile("cp.async.wait_group 1;" ::: "memory");
        } else {
            asm volatile("cp.async.wait_group 0;" ::: "memory");
        }
        __syncthreads();

        const uint32_t AHo = s * OSTG;
        const uint32_t ALo = AHo + OBUF;
        const uint32_t BHo = AHo + 2 * OBUF;
        const uint32_t BLo = AHo + 3 * OBUF;

#pragma unroll
        for (int ks = 0; ks < 2; ks++) {
            uint32_t ah[2][4], al[2][4];
#pragma unroll
            for (int mi = 0; mi < 2; mi++) {
                const uint32_t rb = (wm + mi * 16 + g) * OSTRB + ks * 32 + t * 4;
                ah[mi][0] = *reinterpret_cast<const uint32_t*>(sm + AHo + rb);
                ah[mi][1] = *reinterpret_cast<const uint32_t*>(sm + AHo + rb + 8 * OSTRB);
                ah[mi][2] = *reinterpret_cast<const uint32_t*>(sm + AHo + rb + 16);
                ah[mi][3] = *reinterpret_cast<const uint32_t*>(sm + AHo + rb + 8 * OSTRB + 16);
                al[mi][0] = *reinterpret_cast<const uint32_t*>(sm + ALo + rb);
                al[mi][1] = *reinterpret_cast<const uint32_t*>(sm + ALo + rb + 8 * OSTRB);
                al[mi][2] = *reinterpret_cast<const uint32_t*>(sm + ALo + rb + 16);
                al[mi][3] = *reinterpret_cast<const uint32_t*>(sm + ALo + rb + 8 * OSTRB + 16);
            }
#pragma unroll
            for (int ni = 0; ni < 8; ni++) {
                const uint32_t rb = (wn + ni * 8 + g) * OSTRB + ks * 32 + t * 4;
                uint32_t bh0 = *reinterpret_cast<const uint32_t*>(sm + BHo + rb);
                uint32_t bh1 = *reinterpret_cast<const uint32_t*>(sm + BHo + rb + 16);
                uint32_t bl0 = *reinterpret_cast<const uint32_t*>(sm + BLo + rb);
                uint32_t bl1 = *reinterpret_cast<const uint32_t*>(sm + BLo + rb + 16);
#pragma unroll
                for (int mi = 0; mi < 2; mi++) {
                    mma16816(acc[mi][ni], ah[mi], bh0, bh1);
                    mma16816(acc[mi][ni], ah[mi], bl0, bl1);
                    mma16816(acc[mi][ni], al[mi], bh0, bh1);
                }
            }
        }
        __syncthreads();
    }

#pragma unroll
    for (int mi = 0; mi < 2; mi++) {
        const int r1 = m0 + wm + mi * 16 + g;
        const int r2 = r1 + 8;
#pragma unroll
        for (int ni = 0; ni < 8; ni++) {
            const int col = n0 + wn + ni * 8 + 2 * t;
            float2 bv = *reinterpret_cast<const float2*>(bias + col);
            *reinterpret_cast<float2*>(C + (size_t)r1 * EMB + col) =
                make_float2(acc[mi][ni][0] + bv.x, acc[mi][ni][1] + bv.y);
            *reinterpret_cast<float2*>(C + (size_t)r2 * EMB + col) =
                make_float2(acc[mi][ni][2] + bv.x, acc[mi][ni][3] + bv.y);
        }
    }
}

// ---------------------------------------------------------------------------
extern "C" void kernel_launch(void* const* d_in, const int* in_sizes, int n_in,
                              void* d_out, int out_size)
{
    const float* values  = (const float*)d_in[0];
    const float* keys    = (const float*)d_in[1];
    const float* queries = (const float*)d_in[2];
    const float* Wv      = (const float*)d_in[3];
    const float* Wk      = (const float*)d_in[4];
    const float* Wq      = (const float*)d_in[5];
    const float* Wo      = (const float*)d_in[6];
    const float* bo      = (const float*)d_in[7];
    float* out = (float*)d_out;

    static bool attr_set = false;
    if (!attr_set) {
        cudaFuncSetAttribute(attn_kernel,
                             cudaFuncAttributeMaxDynamicSharedMemorySize, SM_ATT);
        cudaFuncSetAttribute(out_proj_kernel,
                             cudaFuncAttributeMaxDynamicSharedMemorySize, SM_GEMM);
        attr_set = true;
    }

    wo_split_kernel<<<EMB * EMB / 1024, 256>>>(Wo);
    qkv_proj_kernel<<<(BHN * LSEQ) / 256, 256>>>(queries, keys, values, Wq, Wk, Wv);

    dim3 g2(LSEQ / 128, BHN);
    attn_kernel<<<g2, 256, SM_ATT>>>();

    dim3 g3(EMB / 128, (NB * LSEQ) / 128);
    out_proj_kernel<<<g3, 256, SM_GEMM>>>(bo, out);
}

// round 8
// speedup vs baseline: 1.2556x; 1.1698x over previous
#include <cuda_runtime.h>
#include <cuda_bf16.h>
#include <math.h>
#include <stdint.h>

#define NB   4
#define LSEQ 2048
#define EMB  1024
#define NH   16
#define HD   64
#define BHN  (NB*NH)
// Q pre-scale: (1/sqrt(EMB)) * log2(e)  -> scores come out in log2 domain
#define QS   (0.04508422f)

// ---------------- scratch ----------------
__device__ __nv_bfloat16 g_qh[BHN*LSEQ*HD];   // [bh][l][d]  (pre-scaled, linear)
__device__ __nv_bfloat16 g_ql[BHN*LSEQ*HD];
__device__ __nv_bfloat16 g_kh[BHN*LSEQ*HD];   // [bh][l][d]  XOR-swizzled 16B chunks
__device__ __nv_bfloat16 g_kl[BHN*LSEQ*HD];
__device__ __nv_bfloat16 g_vh[BHN*LSEQ*HD];   // [bh][l][d]  XOR-swizzled 16B chunks
__device__ __nv_bfloat16 g_vl[BHN*LSEQ*HD];
// attention out, TILED: [mb 64][kb 32][128 rows][40 bf16 (32 data + 8 pad)]
__device__ __nv_bfloat16 g_aoh_t[64*32*128*40];
__device__ __nv_bfloat16 g_aol_t[64*32*128*40];
// Wo, TILED: [nb 8][kb 32][128][40]
__device__ __nv_bfloat16 g_woh_t[8*32*128*40];
__device__ __nv_bfloat16 g_wol_t[8*32*128*40];

__device__ __forceinline__ uint32_t pack2(__nv_bfloat16 a, __nv_bfloat16 b) {
    return (uint32_t)__bfloat16_as_ushort(a) | ((uint32_t)__bfloat16_as_ushort(b) << 16);
}
__device__ __forceinline__ uint32_t smem_u32(const void* p) {
    uint32_t a;
    asm("{ .reg .u64 t; cvta.to.shared.u64 t, %1; cvt.u32.u64 %0, t; }" : "=r"(a) : "l"(p));
    return a;
}
__device__ __forceinline__ float ex2f(float x) {
    float y; asm("ex2.approx.f32 %0, %1;" : "=f"(y) : "f"(x)); return y;
}
__device__ __forceinline__ void mma16816(float* c, const uint32_t* a,
                                         uint32_t b0, uint32_t b1) {
    asm volatile("mma.sync.aligned.m16n8k16.row.col.f32.bf16.bf16.f32 "
        "{%0,%1,%2,%3}, {%4,%5,%6,%7}, {%8,%9}, {%0,%1,%2,%3};"
        : "+f"(c[0]), "+f"(c[1]), "+f"(c[2]), "+f"(c[3])
        : "r"(a[0]), "r"(a[1]), "r"(a[2]), "r"(a[3]), "r"(b0), "r"(b1));
}
#define LDMX4(r0, r1, r2, r3, addr) \
    asm volatile("ldmatrix.sync.aligned.m8n8.x4.shared.b16 {%0,%1,%2,%3}, [%4];" \
        : "=r"(r0), "=r"(r1), "=r"(r2), "=r"(r3) : "r"(addr))
#define LDMX4T(r0, r1, r2, r3, addr) \
    asm volatile("ldmatrix.sync.aligned.m8n8.x4.trans.shared.b16 {%0,%1,%2,%3}, [%4];" \
        : "=r"(r0), "=r"(r1), "=r"(r2), "=r"(r3) : "r"(addr))

#define CP_BULK(dst, src, bytes, mbar) \
    asm volatile("cp.async.bulk.shared::cta.global.mbarrier::complete_tx::bytes [%0], [%1], %2, [%3];" \
        :: "r"(dst), "l"(src), "r"((uint32_t)(bytes)), "r"(mbar) : "memory")
#define MBAR_INIT(a, c) \
    asm volatile("mbarrier.init.shared.b64 [%0], %1;" :: "r"(a), "r"((uint32_t)(c)) : "memory")
#define MBAR_EXPECT_TX(a, tx) \
    asm volatile("mbarrier.arrive.expect_tx.shared.b64 _, [%0], %1;" :: "r"(a), "r"((uint32_t)(tx)) : "memory")
#define MBAR_WAIT(mbar, par) do {                                              \
    uint32_t _m = (mbar), _p = (par), _d;                                      \
    asm volatile("{\n\t.reg .pred p;\n\t"                                      \
        "mbarrier.try_wait.parity.acquire.cta.shared::cta.b64 p, [%1], %2;\n\t"\
        "selp.b32 %0, 1, 0, p;\n\t}" : "=r"(_d) : "r"(_m), "r"(_p) : "memory");\
    if (!_d) {                                                                 \
        asm volatile("{\n\t.reg .pred P1;\n\t"                                 \
            "W_%=:\n\t"                                                        \
            "mbarrier.try_wait.parity.acquire.cta.shared::cta.b64 P1, [%0], %1, 0x989680;\n\t" \
            "@P1 bra.uni D_%=;\n\t"                                            \
            "bra.uni W_%=;\n\t"                                                \
            "D_%=:\n\t}" :: "r"(_m), "r"(_p) : "memory");                      \
    }                                                                          \
} while (0)

// ---------------------------------------------------------------------------
// Kernel 0: split Wo (fp32) into bf16 hi/lo, TILED [nb][kb][128][40]
// ---------------------------------------------------------------------------
__global__ void __launch_bounds__(256) wo_split_kernel(const float* __restrict__ Wo)
{
    const int i4 = (blockIdx.x * 256 + threadIdx.x) * 4;  // 4 floats
    const int e = i4 >> 10, k = i4 & 1023;
    float4 w = *reinterpret_cast<const float4*>(Wo + i4);
    __nv_bfloat16 h0 = __float2bfloat16(w.x), h1 = __float2bfloat16(w.y);
    __nv_bfloat16 h2 = __float2bfloat16(w.z), h3 = __float2bfloat16(w.w);
    const int nb = e >> 7, er = e & 127, kb = k >> 5, c = k & 31;
    const size_t base = ((size_t)(nb * 32 + kb) * 128 + er) * 40 + c;   // bf16 idx, c%4==0
    uint32_t* oh = reinterpret_cast<uint32_t*>(g_woh_t + base);
    uint32_t* ol = reinterpret_cast<uint32_t*>(g_wol_t + base);
    oh[0] = pack2(h0, h1); oh[1] = pack2(h2, h3);
    ol[0] = pack2(__float2bfloat16(w.x - __bfloat162float(h0)),
                  __float2bfloat16(w.y - __bfloat162float(h1)));
    ol[1] = pack2(__float2bfloat16(w.z - __bfloat162float(h2)),
                  __float2bfloat16(w.w - __bfloat162float(h3)));
}

// ---------------------------------------------------------------------------
// Kernel 1: fused QKV projection. Q linear; K,V stored with 16B-chunk XOR
// swizzle (chunk ^= row&7) so linear bulk-copies land bank-conflict-free.
// ---------------------------------------------------------------------------
__global__ void __launch_bounds__(256) qkv_proj_kernel(
    const float* __restrict__ queries, const float* __restrict__ keys,
    const float* __restrict__ values,
    const float* __restrict__ Wq, const float* __restrict__ Wk,
    const float* __restrict__ Wv)
{
    __shared__ float Wqs[64][64];
    __shared__ float Wks[64][64];
    __shared__ float Wvs[64][64];
    const int tid = threadIdx.x;
#pragma unroll
    for (int u = 0; u < 4; u++) {
        int idx = tid + u * 256;
        reinterpret_cast<float4*>(Wqs)[idx] = reinterpret_cast<const float4*>(Wq)[idx];
        reinterpret_cast<float4*>(Wks)[idx] = reinterpret_cast<const float4*>(Wk)[idx];
        reinterpret_cast<float4*>(Wvs)[idx] = reinterpret_cast<const float4*>(Wv)[idx];
    }
    __syncthreads();

    const int r  = blockIdx.x * 256 + tid;
    const int bh = r >> 11;
    const int l  = r & 2047;
    const int n  = bh >> 4;
    const int h  = bh & 15;
    const size_t in_off = (size_t)n * LSEQ * EMB + (size_t)l * EMB + (size_t)h * HD;
    const int lsw = l & 7;   // swizzle key

    {   // Q (scaled), linear layout
        float4 xr[16];
#pragma unroll
        for (int i = 0; i < 16; i++) xr[i] = reinterpret_cast<const float4*>(queries + in_off)[i];
        uint32_t* oh = reinterpret_cast<uint32_t*>(g_qh + (size_t)r * HD);
        uint32_t* ol = reinterpret_cast<uint32_t*>(g_ql + (size_t)r * HD);
#pragma unroll 4
        for (int e2 = 0; e2 < 32; e2++) {
            float a0 = 0.f, a1 = 0.f;
            const float4* w0 = reinterpret_cast<const float4*>(Wqs[2*e2]);
            const float4* w1 = reinterpret_cast<const float4*>(Wqs[2*e2+1]);
#pragma unroll
            for (int i = 0; i < 16; i++) {
                float4 x = xr[i], u = w0[i], v = w1[i];
                a0 = fmaf(x.x,u.x,fmaf(x.y,u.y,fmaf(x.z,u.z,fmaf(x.w,u.w,a0))));
                a1 = fmaf(x.x,v.x,fmaf(x.y,v.y,fmaf(x.z,v.z,fmaf(x.w,v.w,a1))));
            }
            a0 *= QS; a1 *= QS;
            __nv_bfloat16 h0 = __float2bfloat16(a0), h1 = __float2bfloat16(a1);
            oh[e2] = pack2(h0, h1);
            ol[e2] = pack2(__float2bfloat16(a0 - __bfloat162float(h0)),
                           __float2bfloat16(a1 - __bfloat162float(h1)));
        }
    }
    {   // K, swizzled layout
        float4 xr[16];
#pragma unroll
        for (int i = 0; i < 16; i++) xr[i] = reinterpret_cast<const float4*>(keys + in_off)[i];
        uint32_t* oh = reinterpret_cast<uint32_t*>(g_kh + (size_t)r * HD);
        uint32_t* ol = reinterpret_cast<uint32_t*>(g_kl + (size_t)r * HD);
#pragma unroll 4
        for (int e2 = 0; e2 < 32; e2++) {
            float a0 = 0.f, a1 = 0.f;
            const float4* w0 = reinterpret_cast<const float4*>(Wks[2*e2]);
            const float4* w1 = reinterpret_cast<const float4*>(Wks[2*e2+1]);
#pragma unroll
            for (int i = 0; i < 16; i++) {
                float4 x = xr[i], u = w0[i], v = w1[i];
                a0 = fmaf(x.x,u.x,fmaf(x.y,u.y,fmaf(x.z,u.z,fmaf(x.w,u.w,a0))));
                a1 = fmaf(x.x,v.x,fmaf(x.y,v.y,fmaf(x.z,v.z,fmaf(x.w,v.w,a1))));
            }
            __nv_bfloat16 h0 = __float2bfloat16(a0), h1 = __float2bfloat16(a1);
            const int sw = ((((e2 >> 2) ^ lsw)) << 2) | (e2 & 3);
            oh[sw] = pack2(h0, h1);
            ol[sw] = pack2(__float2bfloat16(a0 - __bfloat162float(h0)),
                           __float2bfloat16(a1 - __bfloat162float(h1)));
        }
    }
    {   // V, swizzled layout
        float4 xr[16];
#pragma unroll
        for (int i = 0; i < 16; i++) xr[i] = reinterpret_cast<const float4*>(values + in_off)[i];
        uint32_t* oh = reinterpret_cast<uint32_t*>(g_vh + (size_t)r * HD);
        uint32_t* ol = reinterpret_cast<uint32_t*>(g_vl + (size_t)r * HD);
#pragma unroll 4
        for (int e2 = 0; e2 < 32; e2++) {
            float a0 = 0.f, a1 = 0.f;
            const float4* w0 = reinterpret_cast<const float4*>(Wvs[2*e2]);
            const float4* w1 = reinterpret_cast<const float4*>(Wvs[2*e2+1]);
#pragma unroll
            for (int i = 0; i < 16; i++) {
                float4 x = xr[i], u = w0[i], v = w1[i];
                a0 = fmaf(x.x,u.x,fmaf(x.y,u.y,fmaf(x.z,u.z,fmaf(x.w,u.w,a0))));
                a1 = fmaf(x.x,v.x,fmaf(x.y,v.y,fmaf(x.z,v.z,fmaf(x.w,v.w,a1))));
            }
            __nv_bfloat16 h0 = __float2bfloat16(a0), h1 = __float2bfloat16(a1);
            const int sw = ((((e2 >> 2) ^ lsw)) << 2) | (e2 & 3);
            oh[sw] = pack2(h0, h1);
            ol[sw] = pack2(__float2bfloat16(a0 - __bfloat162float(h0)),
                           __float2bfloat16(a1 - __bfloat162float(h1)));
        }
    }
}

// ---------------------------------------------------------------------------
// Kernel 2: flash attention. 8 warps x 16 q-rows, 2 CTAs/SM.
// cp.async.bulk double-buffered stages (4 x 8KB), XOR-swizzled smem.
// ---------------------------------------------------------------------------
#define ABUF 8192
#define ASTG 32768
#define SM_ATT 65600    // 2 stages + mbars at +65536, +65544

__global__ void __launch_bounds__(256, 2) attn_kernel()
{
    extern __shared__ char sm[];
    const uint32_t smb = smem_u32(sm);
    const uint32_t mb[2] = {smb + 65536, smb + 65544};
    const int tid = threadIdx.x, wid = tid >> 5, lane = tid & 31;
    const int g = lane >> 2, t = lane & 3;
    const int bh = blockIdx.y;
    const int q0 = blockIdx.x * 128;
    const int warp_q = q0 + wid * 16;

    const int lm = lane >> 3, lr = lane & 7;
    const int kcb = lm & 1;                                // K chunk low bit
    const uint32_t krb = (uint32_t)((8 * (lm >> 1) + lr) * 128);
    const int vcb = lm >> 1;                               // V chunk high bit
    const uint32_t vrb = (uint32_t)(((lm & 1) * 8 + lr) * 128);

    if (tid == 0) { MBAR_INIT(mb[0], 1); MBAR_INIT(mb[1], 1); }
    __syncthreads();

    // ---- Q fragments (hi/lo) in registers (linear global layout) ----
    uint32_t qh[4][4], ql[4][4];
    {
        const uint32_t* bhp = reinterpret_cast<const uint32_t*>(g_qh) + ((size_t)bh * LSEQ + warp_q) * 32;
        const uint32_t* blp = reinterpret_cast<const uint32_t*>(g_ql) + ((size_t)bh * LSEQ + warp_q) * 32;
#pragma unroll
        for (int ks = 0; ks < 4; ks++) {
            qh[ks][0] = bhp[(size_t)g * 32 + 8*ks + t];
            qh[ks][1] = bhp[(size_t)(g+8) * 32 + 8*ks + t];
            qh[ks][2] = bhp[(size_t)g * 32 + 8*ks + t + 4];
            qh[ks][3] = bhp[(size_t)(g+8) * 32 + 8*ks + t + 4];
            ql[ks][0] = blp[(size_t)g * 32 + 8*ks + t];
            ql[ks][1] = blp[(size_t)(g+8) * 32 + 8*ks + t];
            ql[ks][2] = blp[(size_t)g * 32 + 8*ks + t + 4];
            ql[ks][3] = blp[(size_t)(g+8) * 32 + 8*ks + t + 4];
        }
    }

    auto issue_stage = [&](int kt, int s) {
        const uint32_t sb = smb + s * ASTG;
        const size_t go = ((size_t)bh * LSEQ + kt * 64) * HD;  // 8KB contiguous
        MBAR_EXPECT_TX(mb[s], 4 * ABUF);
        CP_BULK(sb,            (const char*)g_kh + go * 2, ABUF, mb[s]);
        CP_BULK(sb + ABUF,     (const char*)g_kl + go * 2, ABUF, mb[s]);
        CP_BULK(sb + 2*ABUF,   (const char*)g_vh + go * 2, ABUF, mb[s]);
        CP_BULK(sb + 3*ABUF,   (const char*)g_vl + go * 2, ABUF, mb[s]);
    };

    float o[8][4];
#pragma unroll
    for (int i = 0; i < 8; i++)
#pragma unroll
        for (int j = 0; j < 4; j++) o[i][j] = 0.f;
    float ls0 = 0.f, ls1 = 0.f;

    if (tid == 0) issue_stage(0, 0);

    for (int kt = 0; kt < 32; kt++) {
        const int s = kt & 1;
        if (kt < 31 && tid == 0) issue_stage(kt + 1, s ^ 1);
        MBAR_WAIT(mb[s], (kt >> 1) & 1);

        const uint32_t KHb = smb + s * ASTG;
        const uint32_t KLb = KHb + ABUF;
        const uint32_t VHb = KHb + 2 * ABUF;
        const uint32_t VLb = KHb + 3 * ABUF;

#pragma unroll
        for (int half = 0; half < 2; half++) {
            const uint32_t hoff = half * 4096;   // 32 key rows * 128B

            // ---- S (3-pass) over 32 keys ----
            float sc[4][4];
#pragma unroll
            for (int nt = 0; nt < 4; nt++)
#pragma unroll
                for (int j = 0; j < 4; j++) sc[nt][j] = 0.f;

#pragma unroll
            for (int ks = 0; ks < 4; ks++) {
                const uint32_t csw = (uint32_t)((((ks << 1) | kcb) ^ lr) << 4);
                uint32_t kf[8], lf[8];
                LDMX4(kf[0], kf[1], kf[2], kf[3], KHb + hoff + krb + csw);
                LDMX4(kf[4], kf[5], kf[6], kf[7], KHb + hoff + 2048 + krb + csw);
                LDMX4(lf[0], lf[1], lf[2], lf[3], KLb + hoff + krb + csw);
                LDMX4(lf[4], lf[5], lf[6], lf[7], KLb + hoff + 2048 + krb + csw);
#pragma unroll
                for (int nt = 0; nt < 4; nt++) {
                    mma16816(sc[nt], qh[ks], kf[2*nt], kf[2*nt+1]);
                    mma16816(sc[nt], qh[ks], lf[2*nt], lf[2*nt+1]);
                    mma16816(sc[nt], ql[ks], kf[2*nt], kf[2*nt+1]);
                }
            }

            // ---- softmax: exp2, lsum, P hi/lo A-fragments ----
            uint32_t ph[2][4], pl[2][4];
#pragma unroll
            for (int nt = 0; nt < 4; nt++) {
                float p0 = ex2f(sc[nt][0]);
                float p1 = ex2f(sc[nt][1]);
                float p2 = ex2f(sc[nt][2]);
                float p3 = ex2f(sc[nt][3]);
                ls0 += p0 + p1;
                ls1 += p2 + p3;
                __nv_bfloat16 h0 = __float2bfloat16(p0), h1 = __float2bfloat16(p1);
                __nv_bfloat16 h2 = __float2bfloat16(p2), h3 = __float2bfloat16(p3);
                const int kc = nt >> 1, su = (nt & 1) * 2;
                ph[kc][su + 0] = pack2(h0, h1);
                ph[kc][su + 1] = pack2(h2, h3);
                pl[kc][su + 0] = pack2(__float2bfloat16(p0 - __bfloat162float(h0)),
                                       __float2bfloat16(p1 - __bfloat162float(h1)));
                pl[kc][su + 1] = pack2(__float2bfloat16(p2 - __bfloat162float(h2)),
                                       __float2bfloat16(p3 - __bfloat162float(h3)));
            }

            // ---- PV (3-pass): O += Ph*Vh + Ph*Vl + Pl*Vh, V^T via ldmatrix.trans ----
#pragma unroll
            for (int kc = 0; kc < 2; kc++) {
                const uint32_t kb = hoff + kc * 2048;   // 16 key rows
#pragma unroll
                for (int db = 0; db < 4; db++) {
                    const uint32_t csw = (uint32_t)((((db << 1) | vcb) ^ lr) << 4);
                    uint32_t vhf[4], vlf[4];
                    LDMX4T(vhf[0], vhf[1], vhf[2], vhf[3], VHb + kb + vrb + csw);
                    LDMX4T(vlf[0], vlf[1], vlf[2], vlf[3], VLb + kb + vrb + csw);
                    mma16816(o[2*db],     ph[kc], vhf[0], vhf[1]);
                    mma16816(o[2*db],     ph[kc], vlf[0], vlf[1]);
                    mma16816(o[2*db],     pl[kc], vhf[0], vhf[1]);
                    mma16816(o[2*db+1],   ph[kc], vhf[2], vhf[3]);
                    mma16816(o[2*db+1],   ph[kc], vlf[2], vlf[3]);
                    mma16816(o[2*db+1],   pl[kc], vhf[2], vhf[3]);
                }
            }
        }
        __syncthreads();
    }

    // ---- epilogue: normalize, split hi/lo bf16, write TILED layout ----
    ls0 += __shfl_xor_sync(0xffffffffu, ls0, 1);
    ls0 += __shfl_xor_sync(0xffffffffu, ls0, 2);
    ls1 += __shfl_xor_sync(0xffffffffu, ls1, 1);
    ls1 += __shfl_xor_sync(0xffffffffu, ls1, 2);
    const float inv0 = 1.f / ls0, inv1 = 1.f / ls1;

    const int n = bh >> 4, h = bh & 15;
    const int gt1 = n * LSEQ + warp_q + g;     // global token rows
    const int gt2 = gt1 + 8;
    const int mb1 = gt1 >> 7, mr1 = gt1 & 127;
    const int mb2 = gt2 >> 7, mr2 = gt2 & 127;
#pragma unroll
    for (int nd = 0; nd < 8; nd++) {
        const int dcol = 8 * nd + 2 * t;
        const int kb = h * 2 + (dcol >> 5);
        const int c = dcol & 31;
        const size_t i1 = (((size_t)(mb1 * 32 + kb) * 128 + mr1) * 40 + c) >> 1;  // uint32 idx
        const size_t i2 = (((size_t)(mb2 * 32 + kb) * 128 + mr2) * 40 + c) >> 1;
        float v0 = o[nd][0] * inv0, v1 = o[nd][1] * inv0;
        float v2 = o[nd][2] * inv1, v3 = o[nd][3] * inv1;
        __nv_bfloat16 h0 = __float2bfloat16(v0), h1 = __float2bfloat16(v1);
        __nv_bfloat16 h2 = __float2bfloat16(v2), h3 = __float2bfloat16(v3);
        reinterpret_cast<uint32_t*>(g_aoh_t)[i1] = pack2(h0, h1);
        reinterpret_cast<uint32_t*>(g_aol_t)[i1] =
            pack2(__float2bfloat16(v0 - __bfloat162float(h0)),
                  __float2bfloat16(v1 - __bfloat162float(h1)));
        reinterpret_cast<uint32_t*>(g_aoh_t)[i2] = pack2(h2, h3);
        reinterpret_cast<uint32_t*>(g_aol_t)[i2] =
            pack2(__float2bfloat16(v2 - __bfloat162float(h2)),
                  __float2bfloat16(v3 - __bfloat162float(h3)));
    }
}

// ---------------------------------------------------------------------------
// Kernel 3: output projection on HMMA, cp.async.bulk tiled stages, 2 CTAs/SM.
// ---------------------------------------------------------------------------
#define OSTRB 80
#define OBUF  10240
#define OSTG  40960
#define SM_GEMM 81984   // 2 stages + mbars at +81920, +81928

__global__ void __launch_bounds__(256, 2) out_proj_kernel(
    const float* __restrict__ bias, float* __restrict__ C)
{
    extern __shared__ char sm[];
    const uint32_t smb = smem_u32(sm);
    const uint32_t mb[2] = {smb + 81920, smb + 81928};
    const int tid = threadIdx.x, wid = tid >> 5, lane = tid & 31;
    const int g = lane >> 2, t = lane & 3;
    const int m0 = blockIdx.y * 128;
    const int n0 = blockIdx.x * 128;
    const int wm = (wid & 3) * 32;
    const int wn = (wid >> 2) * 64;

    if (tid == 0) { MBAR_INIT(mb[0], 1); MBAR_INIT(mb[1], 1); }
    __syncthreads();

    auto issue_stage = [&](int kt, int s) {
        const uint32_t sb = smb + s * OSTG;
        const size_t ao = (size_t)(blockIdx.y * 32 + kt) * (128 * 40);  // bf16 units
        const size_t wo = (size_t)(blockIdx.x * 32 + kt) * (128 * 40);
        MBAR_EXPECT_TX(mb[s], 4 * OBUF);
        CP_BULK(sb,           (const char*)g_aoh_t + ao * 2, OBUF, mb[s]);
        CP_BULK(sb + OBUF,    (const char*)g_aol_t + ao * 2, OBUF, mb[s]);
        CP_BULK(sb + 2*OBUF,  (const char*)g_woh_t + wo * 2, OBUF, mb[s]);
        CP_BULK(sb + 3*OBUF,  (const char*)g_wol_t + wo * 2, OBUF, mb[s]);
    };

    float acc[2][8][4];
#pragma unroll
    for (int i = 0; i < 2; i++)
#pragma unroll
        for (int j = 0; j < 8; j++)
#pragma unroll
            for (int k = 0; k < 4; k++) acc[i][j][k] = 0.f;

    if (tid == 0) issue_stage(0, 0);

    for (int kt = 0; kt < 32; kt++) {
        const int s = kt & 1;
        if (kt < 31 && tid == 0) issue_stage(kt + 1, s ^ 1);
        MBAR_WAIT(mb[s], (kt >> 1) & 1);

        const uint32_t AHo = s * OSTG;
        const uint32_t ALo = AHo + OBUF;
        const uint32_t BHo = AHo + 2 * OBUF;
        const uint32_t BLo = AHo + 3 * OBUF;

#pragma unroll
        for (int ks = 0; ks < 2; ks++) {
            uint32_t ah[2][4], al[2][4];
#pragma unroll
            for (int mi = 0; mi < 2; mi++) {
                const uint32_t rb = (wm + mi * 16 + g) * OSTRB + ks * 32 + t * 4;
                ah[mi][0] = *reinterpret_cast<const uint32_t*>(sm + AHo + rb);
                ah[mi][1] = *reinterpret_cast<const uint32_t*>(sm + AHo + rb + 8 * OSTRB);
                ah[mi][2] = *reinterpret_cast<const uint32_t*>(sm + AHo + rb + 16);
                ah[mi][3] = *reinterpret_cast<const uint32_t*>(sm + AHo + rb + 8 * OSTRB + 16);
                al[mi][0] = *reinterpret_cast<const uint32_t*>(sm + ALo + rb);
                al[mi][1] = *reinterpret_cast<const uint32_t*>(sm + ALo + rb + 8 * OSTRB);
                al[mi][2] = *reinterpret_cast<const uint32_t*>(sm + ALo + rb + 16);
                al[mi][3] = *reinterpret_cast<const uint32_t*>(sm + ALo + rb + 8 * OSTRB + 16);
            }
#pragma unroll
            for (int ni = 0; ni < 8; ni++) {
                const uint32_t rb = (wn + ni * 8 + g) * OSTRB + ks * 32 + t * 4;
                uint32_t bh0 = *reinterpret_cast<const uint32_t*>(sm + BHo + rb);
                uint32_t bh1 = *reinterpret_cast<const uint32_t*>(sm + BHo + rb + 16);
                uint32_t bl0 = *reinterpret_cast<const uint32_t*>(sm + BLo + rb);
                uint32_t bl1 = *reinterpret_cast<const uint32_t*>(sm + BLo + rb + 16);
#pragma unroll
                for (int mi = 0; mi < 2; mi++) {
                    mma16816(acc[mi][ni], ah[mi], bh0, bh1);
                    mma16816(acc[mi][ni], ah[mi], bl0, bl1);
                    mma16816(acc[mi][ni], al[mi], bh0, bh1);
                }
            }
        }
        __syncthreads();
    }

#pragma unroll
    for (int mi = 0; mi < 2; mi++) {
        const int r1 = m0 + wm + mi * 16 + g;
        const int r2 = r1 + 8;
#pragma unroll
        for (int ni = 0; ni < 8; ni++) {
            const int col = n0 + wn + ni * 8 + 2 * t;
            float2 bv = *reinterpret_cast<const float2*>(bias + col);
            *reinterpret_cast<float2*>(C + (size_t)r1 * EMB + col) =
                make_float2(acc[mi][ni][0] + bv.x, acc[mi][ni][1] + bv.y);
            *reinterpret_cast<float2*>(C + (size_t)r2 * EMB + col) =
                make_float2(acc[mi][ni][2] + bv.x, acc[mi][ni][3] + bv.y);
        }
    }
}

// ---------------------------------------------------------------------------
extern "C" void kernel_launch(void* const* d_in, const int* in_sizes, int n_in,
                              void* d_out, int out_size)
{
    const float* values  = (const float*)d_in[0];
    const float* keys    = (const float*)d_in[1];
    const float* queries = (const float*)d_in[2];
    const float* Wv      = (const float*)d_in[3];
    const float* Wk      = (const float*)d_in[4];
    const float* Wq      = (const float*)d_in[5];
    const float* Wo      = (const float*)d_in[6];
    const float* bo      = (const float*)d_in[7];
    float* out = (float*)d_out;

    static bool attr_set = false;
    if (!attr_set) {
        cudaFuncSetAttribute(attn_kernel,
                             cudaFuncAttributeMaxDynamicSharedMemorySize, SM_ATT);
        cudaFuncSetAttribute(out_proj_kernel,
                             cudaFuncAttributeMaxDynamicSharedMemorySize, SM_GEMM);
        attr_set = true;
    }

    wo_split_kernel<<<EMB * EMB / 1024, 256>>>(Wo);
    qkv_proj_kernel<<<(BHN * LSEQ) / 256, 256>>>(queries, keys, values, Wq, Wk, Wv);

    dim3 g2(LSEQ / 128, BHN);
    attn_kernel<<<g2, 256, SM_ATT>>>();

    dim3 g3(EMB / 128, (NB * LSEQ) / 128);
    out_proj_kernel<<<g3, 256, SM_GEMM>>>(bo, out);
}

// round 9
// speedup vs baseline: 1.8822x; 1.4991x over previous
#include <cuda_runtime.h>
#include <cuda_bf16.h>
#include <cuda_fp16.h>
#include <math.h>
#include <stdint.h>

#define NB   4
#define LSEQ 2048
#define EMB  1024
#define NH   16
#define HD   64
#define BHN  (NB*NH)
// Q pre-scale: (1/sqrt(EMB)) * log2(e)  -> scores come out in log2 domain
#define QS   (0.04508422f)

// ---------------- scratch ----------------
__device__ __half g_qh[BHN*LSEQ*HD];          // fp16 [bh][l][d] (pre-scaled, linear)
__device__ __half g_kh[BHN*LSEQ*HD];          // fp16 [bh][l][d] XOR-swizzled chunks
__device__ __half g_vh[BHN*LSEQ*HD];          // fp16 hi, swizzled
__device__ __half g_vl[BHN*LSEQ*HD];          // fp16 lo, swizzled
// attention out, TILED: [mb 64][kb 32][128 rows][40 bf16 (32 data + 8 pad)]
__device__ __nv_bfloat16 g_aoh_t[64*32*128*40];
__device__ __nv_bfloat16 g_aol_t[64*32*128*40];
// Wo, TILED: [nb 8][kb 32][128][40]
__device__ __nv_bfloat16 g_woh_t[8*32*128*40];
__device__ __nv_bfloat16 g_wol_t[8*32*128*40];

__device__ __forceinline__ uint32_t pack2(__nv_bfloat16 a, __nv_bfloat16 b) {
    return (uint32_t)__bfloat16_as_ushort(a) | ((uint32_t)__bfloat16_as_ushort(b) << 16);
}
__device__ __forceinline__ uint32_t pack2h(__half a, __half b) {
    return (uint32_t)__half_as_ushort(a) | ((uint32_t)__half_as_ushort(b) << 16);
}
__device__ __forceinline__ uint32_t cvt_h2(float a, float b) {   // a -> low half
    uint32_t r; asm("cvt.rn.f16x2.f32 %0, %1, %2;" : "=r"(r) : "f"(b), "f"(a)); return r;
}
__device__ __forceinline__ uint32_t smem_u32(const void* p) {
    uint32_t a;
    asm("{ .reg .u64 t; cvta.to.shared.u64 t, %1; cvt.u32.u64 %0, t; }" : "=r"(a) : "l"(p));
    return a;
}
__device__ __forceinline__ float ex2f(float x) {
    float y; asm("ex2.approx.f32 %0, %1;" : "=f"(y) : "f"(x)); return y;
}
__device__ __forceinline__ void mma16816bf(float* c, const uint32_t* a,
                                           uint32_t b0, uint32_t b1) {
    asm volatile("mma.sync.aligned.m16n8k16.row.col.f32.bf16.bf16.f32 "
        "{%0,%1,%2,%3}, {%4,%5,%6,%7}, {%8,%9}, {%0,%1,%2,%3};"
        : "+f"(c[0]), "+f"(c[1]), "+f"(c[2]), "+f"(c[3])
        : "r"(a[0]), "r"(a[1]), "r"(a[2]), "r"(a[3]), "r"(b0), "r"(b1));
}
__device__ __forceinline__ void mma16816h(float* c, const uint32_t* a,
                                          uint32_t b0, uint32_t b1) {
    asm volatile("mma.sync.aligned.m16n8k16.row.col.f32.f16.f16.f32 "
        "{%0,%1,%2,%3}, {%4,%5,%6,%7}, {%8,%9}, {%0,%1,%2,%3};"
        : "+f"(c[0]), "+f"(c[1]), "+f"(c[2]), "+f"(c[3])
        : "r"(a[0]), "r"(a[1]), "r"(a[2]), "r"(a[3]), "r"(b0), "r"(b1));
}
#define LDMX4(r0, r1, r2, r3, addr) \
    asm volatile("ldmatrix.sync.aligned.m8n8.x4.shared.b16 {%0,%1,%2,%3}, [%4];" \
        : "=r"(r0), "=r"(r1), "=r"(r2), "=r"(r3) : "r"(addr))
#define LDMX4T(r0, r1, r2, r3, addr) \
    asm volatile("ldmatrix.sync.aligned.m8n8.x4.trans.shared.b16 {%0,%1,%2,%3}, [%4];" \
        : "=r"(r0), "=r"(r1), "=r"(r2), "=r"(r3) : "r"(addr))

#define CP_BULK(dst, src, bytes, mbar) \
    asm volatile("cp.async.bulk.shared::cta.global.mbarrier::complete_tx::bytes [%0], [%1], %2, [%3];" \
        :: "r"(dst), "l"(src), "r"((uint32_t)(bytes)), "r"(mbar) : "memory")
#define MBAR_INIT(a, c) \
    asm volatile("mbarrier.init.shared.b64 [%0], %1;" :: "r"(a), "r"((uint32_t)(c)) : "memory")
#define MBAR_EXPECT_TX(a, tx) \
    asm volatile("mbarrier.arrive.expect_tx.shared.b64 _, [%0], %1;" :: "r"(a), "r"((uint32_t)(tx)) : "memory")
#define MBAR_WAIT(mbar, par) do {                                              \
    uint32_t _m = (mbar), _p = (par), _d;                                      \
    asm volatile("{\n\t.reg .pred p;\n\t"                                      \
        "mbarrier.try_wait.parity.acquire.cta.shared::cta.b64 p, [%1], %2;\n\t"\
        "selp.b32 %0, 1, 0, p;\n\t}" : "=r"(_d) : "r"(_m), "r"(_p) : "memory");\
    if (!_d) {                                                                 \
        asm volatile("{\n\t.reg .pred P1;\n\t"                                 \
            "W_%=:\n\t"                                                        \
            "mbarrier.try_wait.parity.acquire.cta.shared::cta.b64 P1, [%0], %1, 0x989680;\n\t" \
            "@P1 bra.uni D_%=;\n\t"                                            \
            "bra.uni W_%=;\n\t"                                                \
            "D_%=:\n\t}" :: "r"(_m), "r"(_p) : "memory");                      \
    }                                                                          \
} while (0)

// ---------------------------------------------------------------------------
// Kernel 0: split Wo (fp32) into bf16 hi/lo, TILED [nb][kb][128][40]
// ---------------------------------------------------------------------------
__global__ void __launch_bounds__(256) wo_split_kernel(const float* __restrict__ Wo)
{
    const int i4 = (blockIdx.x * 256 + threadIdx.x) * 4;
    const int e = i4 >> 10, k = i4 & 1023;
    float4 w = *reinterpret_cast<const float4*>(Wo + i4);
    __nv_bfloat16 h0 = __float2bfloat16(w.x), h1 = __float2bfloat16(w.y);
    __nv_bfloat16 h2 = __float2bfloat16(w.z), h3 = __float2bfloat16(w.w);
    const int nb = e >> 7, er = e & 127, kb = k >> 5, c = k & 31;
    const size_t base = ((size_t)(nb * 32 + kb) * 128 + er) * 40 + c;
    uint32_t* oh = reinterpret_cast<uint32_t*>(g_woh_t + base);
    uint32_t* ol = reinterpret_cast<uint32_t*>(g_wol_t + base);
    oh[0] = pack2(h0, h1); oh[1] = pack2(h2, h3);
    ol[0] = pack2(__float2bfloat16(w.x - __bfloat162float(h0)),
                  __float2bfloat16(w.y - __bfloat162float(h1)));
    ol[1] = pack2(__float2bfloat16(w.z - __bfloat162float(h2)),
                  __float2bfloat16(w.w - __bfloat162float(h3)));
}

// ---------------------------------------------------------------------------
// Kernel 1: fused QKV projection -> fp16. Q,K single; V hi/lo. K,V swizzled.
// ---------------------------------------------------------------------------
__global__ void __launch_bounds__(256) qkv_proj_kernel(
    const float* __restrict__ queries, const float* __restrict__ keys,
    const float* __restrict__ values,
    const float* __restrict__ Wq, const float* __restrict__ Wk,
    const float* __restrict__ Wv)
{
    __shared__ float Wqs[64][64];
    __shared__ float Wks[64][64];
    __shared__ float Wvs[64][64];
    const int tid = threadIdx.x;
#pragma unroll
    for (int u = 0; u < 4; u++) {
        int idx = tid + u * 256;
        reinterpret_cast<float4*>(Wqs)[idx] = reinterpret_cast<const float4*>(Wq)[idx];
        reinterpret_cast<float4*>(Wks)[idx] = reinterpret_cast<const float4*>(Wk)[idx];
        reinterpret_cast<float4*>(Wvs)[idx] = reinterpret_cast<const float4*>(Wv)[idx];
    }
    __syncthreads();

    const int r  = blockIdx.x * 256 + tid;
    const int bh = r >> 11;
    const int l  = r & 2047;
    const int n  = bh >> 4;
    const int h  = bh & 15;
    const size_t in_off = (size_t)n * LSEQ * EMB + (size_t)l * EMB + (size_t)h * HD;
    const int lsw = l & 7;

    {   // Q (scaled), fp16, linear
        float4 xr[16];
#pragma unroll
        for (int i = 0; i < 16; i++) xr[i] = reinterpret_cast<const float4*>(queries + in_off)[i];
        uint32_t* oh = reinterpret_cast<uint32_t*>(g_qh + (size_t)r * HD);
#pragma unroll 4
        for (int e2 = 0; e2 < 32; e2++) {
            float a0 = 0.f, a1 = 0.f;
            const float4* w0 = reinterpret_cast<const float4*>(Wqs[2*e2]);
            const float4* w1 = reinterpret_cast<const float4*>(Wqs[2*e2+1]);
#pragma unroll
            for (int i = 0; i < 16; i++) {
                float4 x = xr[i], u = w0[i], v = w1[i];
                a0 = fmaf(x.x,u.x,fmaf(x.y,u.y,fmaf(x.z,u.z,fmaf(x.w,u.w,a0))));
                a1 = fmaf(x.x,v.x,fmaf(x.y,v.y,fmaf(x.z,v.z,fmaf(x.w,v.w,a1))));
            }
            oh[e2] = cvt_h2(a0 * QS, a1 * QS);
        }
    }
    {   // K, fp16, swizzled
        float4 xr[16];
#pragma unroll
        for (int i = 0; i < 16; i++) xr[i] = reinterpret_cast<const float4*>(keys + in_off)[i];
        uint32_t* oh = reinterpret_cast<uint32_t*>(g_kh + (size_t)r * HD);
#pragma unroll 4
        for (int e2 = 0; e2 < 32; e2++) {
            float a0 = 0.f, a1 = 0.f;
            const float4* w0 = reinterpret_cast<const float4*>(Wks[2*e2]);
            const float4* w1 = reinterpret_cast<const float4*>(Wks[2*e2+1]);
#pragma unroll
            for (int i = 0; i < 16; i++) {
                float4 x = xr[i], u = w0[i], v = w1[i];
                a0 = fmaf(x.x,u.x,fmaf(x.y,u.y,fmaf(x.z,u.z,fmaf(x.w,u.w,a0))));
                a1 = fmaf(x.x,v.x,fmaf(x.y,v.y,fmaf(x.z,v.z,fmaf(x.w,v.w,a1))));
            }
            const int sw = ((((e2 >> 2) ^ lsw)) << 2) | (e2 & 3);
            oh[sw] = cvt_h2(a0, a1);
        }
    }
    {   // V, fp16 hi + lo, swizzled
        float4 xr[16];
#pragma unroll
        for (int i = 0; i < 16; i++) xr[i] = reinterpret_cast<const float4*>(values + in_off)[i];
        uint32_t* oh = reinterpret_cast<uint32_t*>(g_vh + (size_t)r * HD);
        uint32_t* ol = reinterpret_cast<uint32_t*>(g_vl + (size_t)r * HD);
#pragma unroll 4
        for (int e2 = 0; e2 < 32; e2++) {
            float a0 = 0.f, a1 = 0.f;
            const float4* w0 = reinterpret_cast<const float4*>(Wvs[2*e2]);
            const float4* w1 = reinterpret_cast<const float4*>(Wvs[2*e2+1]);
#pragma unroll
            for (int i = 0; i < 16; i++) {
                float4 x = xr[i], u = w0[i], v = w1[i];
                a0 = fmaf(x.x,u.x,fmaf(x.y,u.y,fmaf(x.z,u.z,fmaf(x.w,u.w,a0))));
                a1 = fmaf(x.x,v.x,fmaf(x.y,v.y,fmaf(x.z,v.z,fmaf(x.w,v.w,a1))));
            }
            __half h0 = __float2half_rn(a0), h1 = __float2half_rn(a1);
            const int sw = ((((e2 >> 2) ^ lsw)) << 2) | (e2 & 3);
            oh[sw] = pack2h(h0, h1);
            ol[sw] = pack2h(__float2half_rn(a0 - __half2float(h0)),
                            __float2half_rn(a1 - __half2float(h1)));
        }
    }
}

// ---------------------------------------------------------------------------
// Kernel 2: flash attention fp16. 8 warps x 16 q-rows, 2 CTAs/SM.
// S = 1 pass (Qh*Kh), PV = 2 passes (Ph*Vh + Ph*Vl). cp.async.bulk stages.
// ---------------------------------------------------------------------------
#define ABUF 8192
#define ASTG 24576
#define SM_ATT 49216    // 2 stages (3 x 8KB each) + mbars at +49152, +49160

__global__ void __launch_bounds__(256, 2) attn_kernel()
{
    extern __shared__ char sm[];
    const uint32_t smb = smem_u32(sm);
    const uint32_t mb[2] = {smb + 49152, smb + 49160};
    const int tid = threadIdx.x, wid = tid >> 5, lane = tid & 31;
    const int g = lane >> 2, t = lane & 3;
    const int bh = blockIdx.y;
    const int q0 = blockIdx.x * 128;
    const int warp_q = q0 + wid * 16;

    const int lm = lane >> 3, lr = lane & 7;
    const int kcb = lm & 1;
    const uint32_t krb = (uint32_t)((8 * (lm >> 1) + lr) * 128);
    const int vcb = lm >> 1;
    const uint32_t vrb = (uint32_t)(((lm & 1) * 8 + lr) * 128);

    if (tid == 0) { MBAR_INIT(mb[0], 1); MBAR_INIT(mb[1], 1); }
    __syncthreads();

    // ---- Q fragments (fp16) in registers ----
    uint32_t qh[4][4];
    {
        const uint32_t* bhp = reinterpret_cast<const uint32_t*>(g_qh) + ((size_t)bh * LSEQ + warp_q) * 32;
#pragma unroll
        for (int ks = 0; ks < 4; ks++) {
            qh[ks][0] = bhp[(size_t)g * 32 + 8*ks + t];
            qh[ks][1] = bhp[(size_t)(g+8) * 32 + 8*ks + t];
            qh[ks][2] = bhp[(size_t)g * 32 + 8*ks + t + 4];
            qh[ks][3] = bhp[(size_t)(g+8) * 32 + 8*ks + t + 4];
        }
    }

    auto issue_stage = [&](int kt, int s) {
        const uint32_t sb = smb + s * ASTG;
        const size_t go = ((size_t)bh * LSEQ + kt * 64) * HD;
        MBAR_EXPECT_TX(mb[s], 3 * ABUF);
        CP_BULK(sb,            (const char*)g_kh + go * 2, ABUF, mb[s]);
        CP_BULK(sb + ABUF,     (const char*)g_vh + go * 2, ABUF, mb[s]);
        CP_BULK(sb + 2*ABUF,   (const char*)g_vl + go * 2, ABUF, mb[s]);
    };

    float o[8][4];
#pragma unroll
    for (int i = 0; i < 8; i++)
#pragma unroll
        for (int j = 0; j < 4; j++) o[i][j] = 0.f;
    float ls0 = 0.f, ls1 = 0.f;

    if (tid == 0) issue_stage(0, 0);

    for (int kt = 0; kt < 32; kt++) {
        const int s = kt & 1;
        if (kt < 31 && tid == 0) issue_stage(kt + 1, s ^ 1);
        MBAR_WAIT(mb[s], (kt >> 1) & 1);

        const uint32_t KHb = smb + s * ASTG;
        const uint32_t VHb = KHb + ABUF;
        const uint32_t VLb = KHb + 2 * ABUF;

#pragma unroll
        for (int half = 0; half < 2; half++) {
            const uint32_t hoff = half * 4096;

            // ---- S (1 pass fp16) over 32 keys ----
            float sc[4][4];
#pragma unroll
            for (int nt = 0; nt < 4; nt++)
#pragma unroll
                for (int j = 0; j < 4; j++) sc[nt][j] = 0.f;

#pragma unroll
            for (int ks = 0; ks < 4; ks++) {
                const uint32_t csw = (uint32_t)((((ks << 1) | kcb) ^ lr) << 4);
                uint32_t kf[8];
                LDMX4(kf[0], kf[1], kf[2], kf[3], KHb + hoff + krb + csw);
                LDMX4(kf[4], kf[5], kf[6], kf[7], KHb + hoff + 2048 + krb + csw);
#pragma unroll
                for (int nt = 0; nt < 4; nt++)
                    mma16816h(sc[nt], qh[ks], kf[2*nt], kf[2*nt+1]);
            }

            // ---- softmax: exp2, lsum, P fp16 A-fragments ----
            uint32_t ph[2][4];
#pragma unroll
            for (int nt = 0; nt < 4; nt++) {
                float p0 = ex2f(sc[nt][0]);
                float p1 = ex2f(sc[nt][1]);
                float p2 = ex2f(sc[nt][2]);
                float p3 = ex2f(sc[nt][3]);
                ls0 += p0 + p1;
                ls1 += p2 + p3;
                const int kc = nt >> 1, su = (nt & 1) * 2;
                ph[kc][su + 0] = cvt_h2(p0, p1);
                ph[kc][su + 1] = cvt_h2(p2, p3);
            }

            // ---- PV (2 passes): O += Ph*Vh + Ph*Vl ----
#pragma unroll
            for (int kc = 0; kc < 2; kc++) {
                const uint32_t kb = hoff + kc * 2048;
#pragma unroll
                for (int db = 0; db < 4; db++) {
                    const uint32_t csw = (uint32_t)((((db << 1) | vcb) ^ lr) << 4);
                    uint32_t vhf[4], vlf[4];
                    LDMX4T(vhf[0], vhf[1], vhf[2], vhf[3], VHb + kb + vrb + csw);
                    LDMX4T(vlf[0], vlf[1], vlf[2], vlf[3], VLb + kb + vrb + csw);
                    mma16816h(o[2*db],   ph[kc], vhf[0], vhf[1]);
                    mma16816h(o[2*db],   ph[kc], vlf[0], vlf[1]);
                    mma16816h(o[2*db+1], ph[kc], vhf[2], vhf[3]);
                    mma16816h(o[2*db+1], ph[kc], vlf[2], vlf[3]);
                }
            }
        }
        __syncthreads();
    }

    // ---- epilogue: normalize, split hi/lo bf16, write TILED layout ----
    ls0 += __shfl_xor_sync(0xffffffffu, ls0, 1);
    ls0 += __shfl_xor_sync(0xffffffffu, ls0, 2);
    ls1 += __shfl_xor_sync(0xffffffffu, ls1, 1);
    ls1 += __shfl_xor_sync(0xffffffffu, ls1, 2);
    const float inv0 = 1.f / ls0, inv1 = 1.f / ls1;

    const int n = bh >> 4, h = bh & 15;
    const int gt1 = n * LSEQ + warp_q + g;
    const int gt2 = gt1 + 8;
    const int mb1 = gt1 >> 7, mr1 = gt1 & 127;
    const int mb2 = gt2 >> 7, mr2 = gt2 & 127;
#pragma unroll
    for (int nd = 0; nd < 8; nd++) {
        const int dcol = 8 * nd + 2 * t;
        const int kb = h * 2 + (dcol >> 5);
        const int c = dcol & 31;
        const size_t i1 = (((size_t)(mb1 * 32 + kb) * 128 + mr1) * 40 + c) >> 1;
        const size_t i2 = (((size_t)(mb2 * 32 + kb) * 128 + mr2) * 40 + c) >> 1;
        float v0 = o[nd][0] * inv0, v1 = o[nd][1] * inv0;
        float v2 = o[nd][2] * inv1, v3 = o[nd][3] * inv1;
        __nv_bfloat16 h0 = __float2bfloat16(v0), h1 = __float2bfloat16(v1);
        __nv_bfloat16 h2 = __float2bfloat16(v2), h3 = __float2bfloat16(v3);
        reinterpret_cast<uint32_t*>(g_aoh_t)[i1] = pack2(h0, h1);
        reinterpret_cast<uint32_t*>(g_aol_t)[i1] =
            pack2(__float2bfloat16(v0 - __bfloat162float(h0)),
                  __float2bfloat16(v1 - __bfloat162float(h1)));
        reinterpret_cast<uint32_t*>(g_aoh_t)[i2] = pack2(h2, h3);
        reinterpret_cast<uint32_t*>(g_aol_t)[i2] =
            pack2(__float2bfloat16(v2 - __bfloat162float(h2)),
                  __float2bfloat16(v3 - __bfloat162float(h3)));
    }
}

// ---------------------------------------------------------------------------
// Kernel 3: output projection, bf16 3-pass HMMA, cp.async.bulk, 2 CTAs/SM.
// ---------------------------------------------------------------------------
#define OSTRB 80
#define OBUF  10240
#define OSTG  40960
#define SM_GEMM 81984

__global__ void __launch_bounds__(256, 2) out_proj_kernel(
    const float* __restrict__ bias, float* __restrict__ C)
{
    extern __shared__ char sm[];
    const uint32_t smb = smem_u32(sm);
    const uint32_t mb[2] = {smb + 81920, smb + 81928};
    const int tid = threadIdx.x, wid = tid >> 5, lane = tid & 31;
    const int g = lane >> 2, t = lane & 3;
    const int m0 = blockIdx.y * 128;
    const int n0 = blockIdx.x * 128;
    const int wm = (wid & 3) * 32;
    const int wn = (wid >> 2) * 64;

    if (tid == 0) { MBAR_INIT(mb[0], 1); MBAR_INIT(mb[1], 1); }
    __syncthreads();

    auto issue_stage = [&](int kt, int s) {
        const uint32_t sb = smb + s * OSTG;
        const size_t ao = (size_t)(blockIdx.y * 32 + kt) * (128 * 40);
        const size_t wo = (size_t)(blockIdx.x * 32 + kt) * (128 * 40);
        MBAR_EXPECT_TX(mb[s], 4 * OBUF);
        CP_BULK(sb,           (const char*)g_aoh_t + ao * 2, OBUF, mb[s]);
        CP_BULK(sb + OBUF,    (const char*)g_aol_t + ao * 2, OBUF, mb[s]);
        CP_BULK(sb + 2*OBUF,  (const char*)g_woh_t + wo * 2, OBUF, mb[s]);
        CP_BULK(sb + 3*OBUF,  (const char*)g_wol_t + wo * 2, OBUF, mb[s]);
    };

    float acc[2][8][4];
#pragma unroll
    for (int i = 0; i < 2; i++)
#pragma unroll
        for (int j = 0; j < 8; j++)
#pragma unroll
            for (int k = 0; k < 4; k++) acc[i][j][k] = 0.f;

    if (tid == 0) issue_stage(0, 0);

    for (int kt = 0; kt < 32; kt++) {
        const int s = kt & 1;
        if (kt < 31 && tid == 0) issue_stage(kt + 1, s ^ 1);
        MBAR_WAIT(mb[s], (kt >> 1) & 1);

        const uint32_t AHo = s * OSTG;
        const uint32_t ALo = AHo + OBUF;
        const uint32_t BHo = AHo + 2 * OBUF;
        const uint32_t BLo = AHo + 3 * OBUF;

#pragma unroll
        for (int ks = 0; ks < 2; ks++) {
            uint32_t ah[2][4], al[2][4];
#pragma unroll
            for (int mi = 0; mi < 2; mi++) {
                const uint32_t rb = (wm + mi * 16 + g) * OSTRB + ks * 32 + t * 4;
                ah[mi][0] = *reinterpret_cast<const uint32_t*>(sm + AHo + rb);
                ah[mi][1] = *reinterpret_cast<const uint32_t*>(sm + AHo + rb + 8 * OSTRB);
                ah[mi][2] = *reinterpret_cast<const uint32_t*>(sm + AHo + rb + 16);
                ah[mi][3] = *reinterpret_cast<const uint32_t*>(sm + AHo + rb + 8 * OSTRB + 16);
                al[mi][0] = *reinterpret_cast<const uint32_t*>(sm + ALo + rb);
                al[mi][1] = *reinterpret_cast<const uint32_t*>(sm + ALo + rb + 8 * OSTRB);
                al[mi][2] = *reinterpret_cast<const uint32_t*>(sm + ALo + rb + 16);
                al[mi][3] = *reinterpret_cast<const uint32_t*>(sm + ALo + rb + 8 * OSTRB + 16);
            }
#pragma unroll
            for (int ni = 0; ni < 8; ni++) {
                const uint32_t rb = (wn + ni * 8 + g) * OSTRB + ks * 32 + t * 4;
                uint32_t bh0 = *reinterpret_cast<const uint32_t*>(sm + BHo + rb);
                uint32_t bh1 = *reinterpret_cast<const uint32_t*>(sm + BHo + rb + 16);
                uint32_t bl0 = *reinterpret_cast<const uint32_t*>(sm + BLo + rb);
                uint32_t bl1 = *reinterpret_cast<const uint32_t*>(sm + BLo + rb + 16);
#pragma unroll
                for (int mi = 0; mi < 2; mi++) {
                    mma16816bf(acc[mi][ni], ah[mi], bh0, bh1);
                    mma16816bf(acc[mi][ni], ah[mi], bl0, bl1);
                    mma16816bf(acc[mi][ni], al[mi], bh0, bh1);
                }
            }
        }
        __syncthreads();
    }

#pragma unroll
    for (int mi = 0; mi < 2; mi++) {
        const int r1 = m0 + wm + mi * 16 + g;
        const int r2 = r1 + 8;
#pragma unroll
        for (int ni = 0; ni < 8; ni++) {
            const int col = n0 + wn + ni * 8 + 2 * t;
            float2 bv = *reinterpret_cast<const float2*>(bias + col);
            *reinterpret_cast<float2*>(C + (size_t)r1 * EMB + col) =
                make_float2(acc[mi][ni][0] + bv.x, acc[mi][ni][1] + bv.y);
            *reinterpret_cast<float2*>(C + (size_t)r2 * EMB + col) =
                make_float2(acc[mi][ni][2] + bv.x, acc[mi][ni][3] + bv.y);
        }
    }
}

// ---------------------------------------------------------------------------
extern "C" void kernel_launch(void* const* d_in, const int* in_sizes, int n_in,
                              void* d_out, int out_size)
{
    const float* values  = (const float*)d_in[0];
    const float* keys    = (const float*)d_in[1];
    const float* queries = (const float*)d_in[2];
    const float* Wv      = (const float*)d_in[3];
    const float* Wk      = (const float*)d_in[4];
    const float* Wq      = (const float*)d_in[5];
    const float* Wo      = (const float*)d_in[6];
    const float* bo      = (const float*)d_in[7];
    float* out = (float*)d_out;

    static bool attr_set = false;
    if (!attr_set) {
        cudaFuncSetAttribute(attn_kernel,
                             cudaFuncAttributeMaxDynamicSharedMemorySize, SM_ATT);
        cudaFuncSetAttribute(out_proj_kernel,
                             cudaFuncAttributeMaxDynamicSharedMemorySize, SM_GEMM);
        attr_set = true;
    }

    wo_split_kernel<<<EMB * EMB / 1024, 256>>>(Wo);
    qkv_proj_kernel<<<(BHN * LSEQ) / 256, 256>>>(queries, keys, values, Wq, Wk, Wv);

    dim3 g2(LSEQ / 128, BHN);
    attn_kernel<<<g2, 256, SM_ATT>>>();

    dim3 g3(EMB / 128, (NB * LSEQ) / 128);
    out_proj_kernel<<<g3, 256, SM_GEMM>>>(bo, out);
}

// round 10
// speedup vs baseline: 2.3598x; 1.2537x over previous
#include <cuda_runtime.h>
#include <cuda_bf16.h>
#include <cuda_fp16.h>
#include <math.h>
#include <stdint.h>

#define NB   4
#define LSEQ 2048
#define EMB  1024
#define NH   16
#define HD   64
#define BHN  (NB*NH)
// Q pre-scale: (1/sqrt(EMB)) * log2(e)  -> scores come out in log2 domain
#define QS   (0.04508422f)

// ---------------- scratch ----------------
__device__ __half g_qh[BHN*LSEQ*HD];          // fp16 [bh][l][d] (pre-scaled, linear)
__device__ __half g_kh[BHN*LSEQ*HD];          // fp16 [bh][l][d] XOR-swizzled chunks
__device__ __half g_vh[BHN*LSEQ*HD];          // fp16, swizzled
// attention out, TILED fp16: [mb 64][kb 32][128 rows][40 half (32 data + 8 pad)]
__device__ __half g_ao_t[64*32*128*40];
// Wo, TILED fp16 hi/lo: [nb 8][kb 32][128][40]
__device__ __half g_woh_t[8*32*128*40];
__device__ __half g_wol_t[8*32*128*40];

__device__ __forceinline__ uint32_t pack2h(__half a, __half b) {
    return (uint32_t)__half_as_ushort(a) | ((uint32_t)__half_as_ushort(b) << 16);
}
__device__ __forceinline__ uint32_t cvt_h2(float a, float b) {   // a -> low half
    uint32_t r; asm("cvt.rn.f16x2.f32 %0, %1, %2;" : "=r"(r) : "f"(b), "f"(a)); return r;
}
__device__ __forceinline__ uint32_t smem_u32(const void* p) {
    uint32_t a;
    asm("{ .reg .u64 t; cvta.to.shared.u64 t, %1; cvt.u32.u64 %0, t; }" : "=r"(a) : "l"(p));
    return a;
}
__device__ __forceinline__ float ex2f(float x) {
    float y; asm("ex2.approx.f32 %0, %1;" : "=f"(y) : "f"(x)); return y;
}
__device__ __forceinline__ void mma16816h(float* c, const uint32_t* a,
                                          uint32_t b0, uint32_t b1) {
    asm volatile("mma.sync.aligned.m16n8k16.row.col.f32.f16.f16.f32 "
        "{%0,%1,%2,%3}, {%4,%5,%6,%7}, {%8,%9}, {%0,%1,%2,%3};"
        : "+f"(c[0]), "+f"(c[1]), "+f"(c[2]), "+f"(c[3])
        : "r"(a[0]), "r"(a[1]), "r"(a[2]), "r"(a[3]), "r"(b0), "r"(b1));
}
#define LDMX4(r0, r1, r2, r3, addr) \
    asm volatile("ldmatrix.sync.aligned.m8n8.x4.shared.b16 {%0,%1,%2,%3}, [%4];" \
        : "=r"(r0), "=r"(r1), "=r"(r2), "=r"(r3) : "r"(addr))
#define LDMX4T(r0, r1, r2, r3, addr) \
    asm volatile("ldmatrix.sync.aligned.m8n8.x4.trans.shared.b16 {%0,%1,%2,%3}, [%4];" \
        : "=r"(r0), "=r"(r1), "=r"(r2), "=r"(r3) : "r"(addr))

#define CP_BULK(dst, src, bytes, mbar) \
    asm volatile("cp.async.bulk.shared::cta.global.mbarrier::complete_tx::bytes [%0], [%1], %2, [%3];" \
        :: "r"(dst), "l"(src), "r"((uint32_t)(bytes)), "r"(mbar) : "memory")
#define MBAR_INIT(a, c) \
    asm volatile("mbarrier.init.shared.b64 [%0], %1;" :: "r"(a), "r"((uint32_t)(c)) : "memory")
#define MBAR_EXPECT_TX(a, tx) \
    asm volatile("mbarrier.arrive.expect_tx.shared.b64 _, [%0], %1;" :: "r"(a), "r"((uint32_t)(tx)) : "memory")
#define MBAR_WAIT(mbar, par) do {                                              \
    uint32_t _m = (mbar), _p = (par), _d;                                      \
    asm volatile("{\n\t.reg .pred p;\n\t"                                      \
        "mbarrier.try_wait.parity.acquire.cta.shared::cta.b64 p, [%1], %2;\n\t"\
        "selp.b32 %0, 1, 0, p;\n\t}" : "=r"(_d) : "r"(_m), "r"(_p) : "memory");\
    if (!_d) {                                                                 \
        asm volatile("{\n\t.reg .pred P1;\n\t"                                 \
            "W_%=:\n\t"                                                        \
            "mbarrier.try_wait.parity.acquire.cta.shared::cta.b64 P1, [%0], %1, 0x989680;\n\t" \
            "@P1 bra.uni D_%=;\n\t"                                            \
            "bra.uni W_%=;\n\t"                                                \
            "D_%=:\n\t}" :: "r"(_m), "r"(_p) : "memory");                      \
    }                                                                          \
} while (0)

// ---------------------------------------------------------------------------
// Kernel 0: split Wo (fp32) into fp16 hi/lo, TILED [nb][kb][128][40]
// ---------------------------------------------------------------------------
__global__ void __launch_bounds__(256) wo_split_kernel(const float* __restrict__ Wo)
{
    const int i4 = (blockIdx.x * 256 + threadIdx.x) * 4;
    const int e = i4 >> 10, k = i4 & 1023;
    float4 w = *reinterpret_cast<const float4*>(Wo + i4);
    __half h0 = __float2half_rn(w.x), h1 = __float2half_rn(w.y);
    __half h2 = __float2half_rn(w.z), h3 = __float2half_rn(w.w);
    const int nb = e >> 7, er = e & 127, kb = k >> 5, c = k & 31;
    const size_t base = ((size_t)(nb * 32 + kb) * 128 + er) * 40 + c;
    uint32_t* oh = reinterpret_cast<uint32_t*>(g_woh_t + base);
    uint32_t* ol = reinterpret_cast<uint32_t*>(g_wol_t + base);
    oh[0] = pack2h(h0, h1); oh[1] = pack2h(h2, h3);
    ol[0] = pack2h(__float2half_rn(w.x - __half2float(h0)),
                   __float2half_rn(w.y - __half2float(h1)));
    ol[1] = pack2h(__float2half_rn(w.z - __half2float(h2)),
                   __float2half_rn(w.w - __half2float(h3)));
}

// ---------------------------------------------------------------------------
// Kernel 1: fused QKV projection -> fp16 single. K,V swizzled.
// ---------------------------------------------------------------------------
__global__ void __launch_bounds__(256) qkv_proj_kernel(
    const float* __restrict__ queries, const float* __restrict__ keys,
    const float* __restrict__ values,
    const float* __restrict__ Wq, const float* __restrict__ Wk,
    const float* __restrict__ Wv)
{
    __shared__ float Wqs[64][64];
    __shared__ float Wks[64][64];
    __shared__ float Wvs[64][64];
    const int tid = threadIdx.x;
#pragma unroll
    for (int u = 0; u < 4; u++) {
        int idx = tid + u * 256;
        reinterpret_cast<float4*>(Wqs)[idx] = reinterpret_cast<const float4*>(Wq)[idx];
        reinterpret_cast<float4*>(Wks)[idx] = reinterpret_cast<const float4*>(Wk)[idx];
        reinterpret_cast<float4*>(Wvs)[idx] = reinterpret_cast<const float4*>(Wv)[idx];
    }
    __syncthreads();

    const int r  = blockIdx.x * 256 + tid;
    const int bh = r >> 11;
    const int l  = r & 2047;
    const int n  = bh >> 4;
    const int h  = bh & 15;
    const size_t in_off = (size_t)n * LSEQ * EMB + (size_t)l * EMB + (size_t)h * HD;
    const int lsw = l & 7;

    {   // Q (scaled), fp16, linear
        float4 xr[16];
#pragma unroll
        for (int i = 0; i < 16; i++) xr[i] = reinterpret_cast<const float4*>(queries + in_off)[i];
        uint32_t* oh = reinterpret_cast<uint32_t*>(g_qh + (size_t)r * HD);
#pragma unroll 4
        for (int e2 = 0; e2 < 32; e2++) {
            float a0 = 0.f, a1 = 0.f;
            const float4* w0 = reinterpret_cast<const float4*>(Wqs[2*e2]);
            const float4* w1 = reinterpret_cast<const float4*>(Wqs[2*e2+1]);
#pragma unroll
            for (int i = 0; i < 16; i++) {
                float4 x = xr[i], u = w0[i], v = w1[i];
                a0 = fmaf(x.x,u.x,fmaf(x.y,u.y,fmaf(x.z,u.z,fmaf(x.w,u.w,a0))));
                a1 = fmaf(x.x,v.x,fmaf(x.y,v.y,fmaf(x.z,v.z,fmaf(x.w,v.w,a1))));
            }
            oh[e2] = cvt_h2(a0 * QS, a1 * QS);
        }
    }
    {   // K, fp16, swizzled
        float4 xr[16];
#pragma unroll
        for (int i = 0; i < 16; i++) xr[i] = reinterpret_cast<const float4*>(keys + in_off)[i];
        uint32_t* oh = reinterpret_cast<uint32_t*>(g_kh + (size_t)r * HD);
#pragma unroll 4
        for (int e2 = 0; e2 < 32; e2++) {
            float a0 = 0.f, a1 = 0.f;
            const float4* w0 = reinterpret_cast<const float4*>(Wks[2*e2]);
            const float4* w1 = reinterpret_cast<const float4*>(Wks[2*e2+1]);
#pragma unroll
            for (int i = 0; i < 16; i++) {
                float4 x = xr[i], u = w0[i], v = w1[i];
                a0 = fmaf(x.x,u.x,fmaf(x.y,u.y,fmaf(x.z,u.z,fmaf(x.w,u.w,a0))));
                a1 = fmaf(x.x,v.x,fmaf(x.y,v.y,fmaf(x.z,v.z,fmaf(x.w,v.w,a1))));
            }
            const int sw = ((((e2 >> 2) ^ lsw)) << 2) | (e2 & 3);
            oh[sw] = cvt_h2(a0, a1);
        }
    }
    {   // V, fp16 single, swizzled
        float4 xr[16];
#pragma unroll
        for (int i = 0; i < 16; i++) xr[i] = reinterpret_cast<const float4*>(values + in_off)[i];
        uint32_t* oh = reinterpret_cast<uint32_t*>(g_vh + (size_t)r * HD);
#pragma unroll 4
        for (int e2 = 0; e2 < 32; e2++) {
            float a0 = 0.f, a1 = 0.f;
            const float4* w0 = reinterpret_cast<const float4*>(Wvs[2*e2]);
            const float4* w1 = reinterpret_cast<const float4*>(Wvs[2*e2+1]);
#pragma unroll
            for (int i = 0; i < 16; i++) {
                float4 x = xr[i], u = w0[i], v = w1[i];
                a0 = fmaf(x.x,u.x,fmaf(x.y,u.y,fmaf(x.z,u.z,fmaf(x.w,u.w,a0))));
                a1 = fmaf(x.x,v.x,fmaf(x.y,v.y,fmaf(x.z,v.z,fmaf(x.w,v.w,a1))));
            }
            const int sw = ((((e2 >> 2) ^ lsw)) << 2) | (e2 & 3);
            oh[sw] = cvt_h2(a0, a1);
        }
    }
}

// ---------------------------------------------------------------------------
// Kernel 2: flash attention fp16. 8 warps x 16 q-rows, 2 CTAs/SM.
// S = 1 pass, PV = 1 pass. cp.async.bulk stages (2 x 8KB).
// ---------------------------------------------------------------------------
#define ABUF 8192
#define ASTG 16384
#define SM_ATT 32784    // 2 stages + mbars at +32768

__global__ void __launch_bounds__(256, 2) attn_kernel()
{
    extern __shared__ char sm[];
    const uint32_t smb = smem_u32(sm);
    const uint32_t mb[2] = {smb + 32768, smb + 32776};
    const int tid = threadIdx.x, wid = tid >> 5, lane = tid & 31;
    const int g = lane >> 2, t = lane & 3;
    const int bh = blockIdx.y;
    const int q0 = blockIdx.x * 128;
    const int warp_q = q0 + wid * 16;

    const int lm = lane >> 3, lr = lane & 7;
    const int kcb = lm & 1;
    const uint32_t krb = (uint32_t)((8 * (lm >> 1) + lr) * 128);
    const int vcb = lm >> 1;
    const uint32_t vrb = (uint32_t)(((lm & 1) * 8 + lr) * 128);

    if (tid == 0) { MBAR_INIT(mb[0], 1); MBAR_INIT(mb[1], 1); }
    __syncthreads();

    // ---- Q fragments (fp16) in registers ----
    uint32_t qh[4][4];
    {
        const uint32_t* bhp = reinterpret_cast<const uint32_t*>(g_qh) + ((size_t)bh * LSEQ + warp_q) * 32;
#pragma unroll
        for (int ks = 0; ks < 4; ks++) {
            qh[ks][0] = bhp[(size_t)g * 32 + 8*ks + t];
            qh[ks][1] = bhp[(size_t)(g+8) * 32 + 8*ks + t];
            qh[ks][2] = bhp[(size_t)g * 32 + 8*ks + t + 4];
            qh[ks][3] = bhp[(size_t)(g+8) * 32 + 8*ks + t + 4];
        }
    }

    auto issue_stage = [&](int kt, int s) {
        const uint32_t sb = smb + s * ASTG;
        const size_t go = ((size_t)bh * LSEQ + kt * 64) * HD;
        MBAR_EXPECT_TX(mb[s], 2 * ABUF);
        CP_BULK(sb,            (const char*)g_kh + go * 2, ABUF, mb[s]);
        CP_BULK(sb + ABUF,     (const char*)g_vh + go * 2, ABUF, mb[s]);
    };

    float o[8][4];
#pragma unroll
    for (int i = 0; i < 8; i++)
#pragma unroll
        for (int j = 0; j < 4; j++) o[i][j] = 0.f;
    float ls0 = 0.f, ls1 = 0.f;

    if (tid == 0) issue_stage(0, 0);

    for (int kt = 0; kt < 32; kt++) {
        const int s = kt & 1;
        if (kt < 31 && tid == 0) issue_stage(kt + 1, s ^ 1);
        MBAR_WAIT(mb[s], (kt >> 1) & 1);

        const uint32_t KHb = smb + s * ASTG;
        const uint32_t VHb = KHb + ABUF;

#pragma unroll
        for (int half = 0; half < 2; half++) {
            const uint32_t hoff = half * 4096;

            // ---- S (1 pass fp16) over 32 keys ----
            float sc[4][4];
#pragma unroll
            for (int nt = 0; nt < 4; nt++)
#pragma unroll
                for (int j = 0; j < 4; j++) sc[nt][j] = 0.f;

#pragma unroll
            for (int ks = 0; ks < 4; ks++) {
                const uint32_t csw = (uint32_t)((((ks << 1) | kcb) ^ lr) << 4);
                uint32_t kf[8];
                LDMX4(kf[0], kf[1], kf[2], kf[3], KHb + hoff + krb + csw);
                LDMX4(kf[4], kf[5], kf[6], kf[7], KHb + hoff + 2048 + krb + csw);
#pragma unroll
                for (int nt = 0; nt < 4; nt++)
                    mma16816h(sc[nt], qh[ks], kf[2*nt], kf[2*nt+1]);
            }

            // ---- softmax: exp2, lsum, P fp16 A-fragments ----
            uint32_t ph[2][4];
#pragma unroll
            for (int nt = 0; nt < 4; nt++) {
                float p0 = ex2f(sc[nt][0]);
                float p1 = ex2f(sc[nt][1]);
                float p2 = ex2f(sc[nt][2]);
                float p3 = ex2f(sc[nt][3]);
                ls0 += p0 + p1;
                ls1 += p2 + p3;
                const int kc = nt >> 1, su = (nt & 1) * 2;
                ph[kc][su + 0] = cvt_h2(p0, p1);
                ph[kc][su + 1] = cvt_h2(p2, p3);
            }

            // ---- PV (1 pass): O += Ph*Vh ----
#pragma unroll
            for (int kc = 0; kc < 2; kc++) {
                const uint32_t kb = hoff + kc * 2048;
#pragma unroll
                for (int db = 0; db < 4; db++) {
                    const uint32_t csw = (uint32_t)((((db << 1) | vcb) ^ lr) << 4);
                    uint32_t vhf[4];
                    LDMX4T(vhf[0], vhf[1], vhf[2], vhf[3], VHb + kb + vrb + csw);
                    mma16816h(o[2*db],   ph[kc], vhf[0], vhf[1]);
                    mma16816h(o[2*db+1], ph[kc], vhf[2], vhf[3]);
                }
            }
        }
        __syncthreads();
    }

    // ---- epilogue: normalize, fp16, write TILED layout ----
    ls0 += __shfl_xor_sync(0xffffffffu, ls0, 1);
    ls0 += __shfl_xor_sync(0xffffffffu, ls0, 2);
    ls1 += __shfl_xor_sync(0xffffffffu, ls1, 1);
    ls1 += __shfl_xor_sync(0xffffffffu, ls1, 2);
    const float inv0 = 1.f / ls0, inv1 = 1.f / ls1;

    const int n = bh >> 4, h = bh & 15;
    const int gt1 = n * LSEQ + warp_q + g;
    const int gt2 = gt1 + 8;
    const int mb1 = gt1 >> 7, mr1 = gt1 & 127;
    const int mb2 = gt2 >> 7, mr2 = gt2 & 127;
#pragma unroll
    for (int nd = 0; nd < 8; nd++) {
        const int dcol = 8 * nd + 2 * t;
        const int kb = h * 2 + (dcol >> 5);
        const int c = dcol & 31;
        const size_t i1 = (((size_t)(mb1 * 32 + kb) * 128 + mr1) * 40 + c) >> 1;
        const size_t i2 = (((size_t)(mb2 * 32 + kb) * 128 + mr2) * 40 + c) >> 1;
        reinterpret_cast<uint32_t*>(g_ao_t)[i1] = cvt_h2(o[nd][0] * inv0, o[nd][1] * inv0);
        reinterpret_cast<uint32_t*>(g_ao_t)[i2] = cvt_h2(o[nd][2] * inv1, o[nd][3] * inv1);
    }
}

// ---------------------------------------------------------------------------
// Kernel 3: output projection, fp16 2-pass (A*Wh + A*Wl), cp.async.bulk.
// ---------------------------------------------------------------------------
#define OSTRB 80
#define OBUF  10240
#define OSTG  30720     // 3 buffers: A, Wh, Wl
#define SM_GEMM 61456   // 2 stages + mbars at +61440

__global__ void __launch_bounds__(256, 2) out_proj_kernel(
    const float* __restrict__ bias, float* __restrict__ C)
{
    extern __shared__ char sm[];
    const uint32_t smb = smem_u32(sm);
    const uint32_t mb[2] = {smb + 61440, smb + 61448};
    const int tid = threadIdx.x, wid = tid >> 5, lane = tid & 31;
    const int g = lane >> 2, t = lane & 3;
    const int m0 = blockIdx.y * 128;
    const int n0 = blockIdx.x * 128;
    const int wm = (wid & 3) * 32;
    const int wn = (wid >> 2) * 64;

    if (tid == 0) { MBAR_INIT(mb[0], 1); MBAR_INIT(mb[1], 1); }
    __syncthreads();

    auto issue_stage = [&](int kt, int s) {
        const uint32_t sb = smb + s * OSTG;
        const size_t ao = (size_t)(blockIdx.y * 32 + kt) * (128 * 40);
        const size_t wo = (size_t)(blockIdx.x * 32 + kt) * (128 * 40);
        MBAR_EXPECT_TX(mb[s], 3 * OBUF);
        CP_BULK(sb,           (const char*)g_ao_t  + ao * 2, OBUF, mb[s]);
        CP_BULK(sb + OBUF,    (const char*)g_woh_t + wo * 2, OBUF, mb[s]);
        CP_BULK(sb + 2*OBUF,  (const char*)g_wol_t + wo * 2, OBUF, mb[s]);
    };

    float acc[2][8][4];
#pragma unroll
    for (int i = 0; i < 2; i++)
#pragma unroll
        for (int j = 0; j < 8; j++)
#pragma unroll
            for (int k = 0; k < 4; k++) acc[i][j][k] = 0.f;

    if (tid == 0) issue_stage(0, 0);

    for (int kt = 0; kt < 32; kt++) {
        const int s = kt & 1;
        if (kt < 31 && tid == 0) issue_stage(kt + 1, s ^ 1);
        MBAR_WAIT(mb[s], (kt >> 1) & 1);

        const uint32_t Ao  = s * OSTG;
        const uint32_t BHo = Ao + OBUF;
        const uint32_t BLo = Ao + 2 * OBUF;

#pragma unroll
        for (int ks = 0; ks < 2; ks++) {
            uint32_t ah[2][4];
#pragma unroll
            for (int mi = 0; mi < 2; mi++) {
                const uint32_t rb = (wm + mi * 16 + g) * OSTRB + ks * 32 + t * 4;
                ah[mi][0] = *reinterpret_cast<const uint32_t*>(sm + Ao + rb);
                ah[mi][1] = *reinterpret_cast<const uint32_t*>(sm + Ao + rb + 8 * OSTRB);
                ah[mi][2] = *reinterpret_cast<const uint32_t*>(sm + Ao + rb + 16);
                ah[mi][3] = *reinterpret_cast<const uint32_t*>(sm + Ao + rb + 8 * OSTRB + 16);
            }
#pragma unroll
            for (int ni = 0; ni < 8; ni++) {
                const uint32_t rb = (wn + ni * 8 + g) * OSTRB + ks * 32 + t * 4;
                uint32_t bh0 = *reinterpret_cast<const uint32_t*>(sm + BHo + rb);
                uint32_t bh1 = *reinterpret_cast<const uint32_t*>(sm + BHo + rb + 16);
                uint32_t bl0 = *reinterpret_cast<const uint32_t*>(sm + BLo + rb);
                uint32_t bl1 = *reinterpret_cast<const uint32_t*>(sm + BLo + rb + 16);
#pragma unroll
                for (int mi = 0; mi < 2; mi++) {
                    mma16816h(acc[mi][ni], ah[mi], bh0, bh1);
                    mma16816h(acc[mi][ni], ah[mi], bl0, bl1);
                }
            }
        }
        __syncthreads();
    }

#pragma unroll
    for (int mi = 0; mi < 2; mi++) {
        const int r1 = m0 + wm + mi * 16 + g;
        const int r2 = r1 + 8;
#pragma unroll
        for (int ni = 0; ni < 8; ni++) {
            const int col = n0 + wn + ni * 8 + 2 * t;
            float2 bv = *reinterpret_cast<const float2*>(bias + col);
            *reinterpret_cast<float2*>(C + (size_t)r1 * EMB + col) =
                make_float2(acc[mi][ni][0] + bv.x, acc[mi][ni][1] + bv.y);
            *reinterpret_cast<float2*>(C + (size_t)r2 * EMB + col) =
                make_float2(acc[mi][ni][2] + bv.x, acc[mi][ni][3] + bv.y);
        }
    }
}

// ---------------------------------------------------------------------------
extern "C" void kernel_launch(void* const* d_in, const int* in_sizes, int n_in,
                              void* d_out, int out_size)
{
    const float* values  = (const float*)d_in[0];
    const float* keys    = (const float*)d_in[1];
    const float* queries = (const float*)d_in[2];
    const float* Wv      = (const float*)d_in[3];
    const float* Wk      = (const float*)d_in[4];
    const float* Wq      = (const float*)d_in[5];
    const float* Wo      = (const float*)d_in[6];
    const float* bo      = (const float*)d_in[7];
    float* out = (float*)d_out;

    static bool attr_set = false;
    if (!attr_set) {
        cudaFuncSetAttribute(attn_kernel,
                             cudaFuncAttributeMaxDynamicSharedMemorySize, SM_ATT);
        cudaFuncSetAttribute(out_proj_kernel,
                             cudaFuncAttributeMaxDynamicSharedMemorySize, SM_GEMM);
        attr_set = true;
    }

    wo_split_kernel<<<EMB * EMB / 1024, 256>>>(Wo);
    qkv_proj_kernel<<<(BHN * LSEQ) / 256, 256>>>(queries, keys, values, Wq, Wk, Wv);

    dim3 g2(LSEQ / 128, BHN);
    attn_kernel<<<g2, 256, SM_ATT>>>();

    dim3 g3(EMB / 128, (NB * LSEQ) / 128);
    out_proj_kernel<<<g3, 256, SM_GEMM>>>(bo, out);
}

// round 11
// speedup vs baseline: 3.0916x; 1.3101x over previous
#include <cuda_runtime.h>
#include <cuda_fp16.h>
#include <math.h>
#include <stdint.h>

#define NB   4
#define LSEQ 2048
#define EMB  1024
#define NH   16
#define HD   64
#define BHN  (NB*NH)
// Q pre-scale: (1/sqrt(EMB)) * log2(e)  -> scores come out in log2 domain
#define QS   (0.04508422f)

// ---------------- scratch ----------------
__device__ __half g_qh[BHN*LSEQ*HD];          // fp16 [bh][l][d] (pre-scaled, linear)
__device__ __half g_kh[BHN*LSEQ*HD];          // fp16 [bh][l][d] XOR-swizzled chunks
__device__ __half g_vh[BHN*LSEQ*HD];          // fp16, swizzled
// attention out, TILED fp16: [mb 64][kb 32][128 rows][40 half (32 data + 8 pad)]
__device__ __half g_ao_t[64*32*128*40];
// Wo, TILED fp16: [nb 8][kb 32][128][40]
__device__ __half g_wo_t[8*32*128*40];

__device__ __forceinline__ uint32_t cvt_h2(float a, float b) {   // a -> low half
    uint32_t r; asm("cvt.rn.f16x2.f32 %0, %1, %2;" : "=r"(r) : "f"(b), "f"(a)); return r;
}
__device__ __forceinline__ uint32_t smem_u32(const void* p) {
    uint32_t a;
    asm("{ .reg .u64 t; cvta.to.shared.u64 t, %1; cvt.u32.u64 %0, t; }" : "=r"(a) : "l"(p));
    return a;
}
__device__ __forceinline__ float ex2f(float x) {
    float y; asm("ex2.approx.f32 %0, %1;" : "=f"(y) : "f"(x)); return y;
}
__device__ __forceinline__ void mma16816h(float* c, const uint32_t* a,
                                          uint32_t b0, uint32_t b1) {
    asm volatile("mma.sync.aligned.m16n8k16.row.col.f32.f16.f16.f32 "
        "{%0,%1,%2,%3}, {%4,%5,%6,%7}, {%8,%9}, {%0,%1,%2,%3};"
        : "+f"(c[0]), "+f"(c[1]), "+f"(c[2]), "+f"(c[3])
        : "r"(a[0]), "r"(a[1]), "r"(a[2]), "r"(a[3]), "r"(b0), "r"(b1));
}
#define LDMX4(r0, r1, r2, r3, addr) \
    asm volatile("ldmatrix.sync.aligned.m8n8.x4.shared.b16 {%0,%1,%2,%3}, [%4];" \
        : "=r"(r0), "=r"(r1), "=r"(r2), "=r"(r3) : "r"(addr))
#define LDMX4T(r0, r1, r2, r3, addr) \
    asm volatile("ldmatrix.sync.aligned.m8n8.x4.trans.shared.b16 {%0,%1,%2,%3}, [%4];" \
        : "=r"(r0), "=r"(r1), "=r"(r2), "=r"(r3) : "r"(addr))

#define CP_BULK(dst, src, bytes, mbar) \
    asm volatile("cp.async.bulk.shared::cta.global.mbarrier::complete_tx::bytes [%0], [%1], %2, [%3];" \
        :: "r"(dst), "l"(src), "r"((uint32_t)(bytes)), "r"(mbar) : "memory")
#define MBAR_INIT(a, c) \
    asm volatile("mbarrier.init.shared.b64 [%0], %1;" :: "r"(a), "r"((uint32_t)(c)) : "memory")
#define MBAR_EXPECT_TX(a, tx) \
    asm volatile("mbarrier.arrive.expect_tx.shared.b64 _, [%0], %1;" :: "r"(a), "r"((uint32_t)(tx)) : "memory")
#define MBAR_WAIT(mbar, par) do {                                              \
    uint32_t _m = (mbar), _p = (par), _d;                                      \
    asm volatile("{\n\t.reg .pred p;\n\t"                                      \
        "mbarrier.try_wait.parity.acquire.cta.shared::cta.b64 p, [%1], %2;\n\t"\
        "selp.b32 %0, 1, 0, p;\n\t}" : "=r"(_d) : "r"(_m), "r"(_p) : "memory");\
    if (!_d) {                                                                 \
        asm volatile("{\n\t.reg .pred P1;\n\t"                                 \
            "W_%=:\n\t"                                                        \
            "mbarrier.try_wait.parity.acquire.cta.shared::cta.b64 P1, [%0], %1, 0x989680;\n\t" \
            "@P1 bra.uni D_%=;\n\t"                                            \
            "bra.uni W_%=;\n\t"                                                \
            "D_%=:\n\t}" :: "r"(_m), "r"(_p) : "memory");                      \
    }                                                                          \
} while (0)

// ---------------------------------------------------------------------------
// Kernel 0: Wo (fp32) -> fp16 TILED [nb][kb][128][40]
// ---------------------------------------------------------------------------
__global__ void __launch_bounds__(256) wo_split_kernel(const float* __restrict__ Wo)
{
    const int i4 = (blockIdx.x * 256 + threadIdx.x) * 4;
    const int e = i4 >> 10, k = i4 & 1023;
    float4 w = *reinterpret_cast<const float4*>(Wo + i4);
    const int nb = e >> 7, er = e & 127, kb = k >> 5, c = k & 31;
    const size_t base = ((size_t)(nb * 32 + kb) * 128 + er) * 40 + c;
    uint32_t* oh = reinterpret_cast<uint32_t*>(g_wo_t + base);
    oh[0] = cvt_h2(w.x, w.y); oh[1] = cvt_h2(w.z, w.w);
}

// ---------------------------------------------------------------------------
// Kernel 1: QKV projection on HMMA. Grid (8 tiles, 64 bh), 256 thr, 8 warps.
// Per weight: load 256x64 fp32 input tile -> fp16 swizzled smem -> 64 MMA/warp.
// ---------------------------------------------------------------------------
#define QKV_SMX 24576          // X tile after 3 x 8KB weights
#define QKV_SMT 57344

__global__ void __launch_bounds__(256) qkv_mma_kernel(
    const float* __restrict__ q_in, const float* __restrict__ k_in,
    const float* __restrict__ v_in,
    const float* __restrict__ Wq, const float* __restrict__ Wk,
    const float* __restrict__ Wv)
{
    extern __shared__ char sm[];
    const uint32_t smb = smem_u32(sm);
    const int tid = threadIdx.x, wid = tid >> 5, lane = tid & 31;
    const int g = lane >> 2, t = lane & 3;
    const int lm = lane >> 3, lr = lane & 7;
    const int bh = blockIdx.y;
    const int tile = blockIdx.x;
    const int n = bh >> 4, h = bh & 15;

    // ---- load 3 weights: fp32 -> fp16, rows of 128B, chunk XOR swizzle ----
    const float* Ws[3] = {Wq, Wk, Wv};
#pragma unroll
    for (int w = 0; w < 3; w++) {
#pragma unroll
        for (int u = 0; u < 2; u++) {
            int cl = tid + u * 256;              // chunk 0..511
            int row = cl >> 3, c = cl & 7;
            float4 f0 = reinterpret_cast<const float4*>(Ws[w])[row * 16 + c * 2];
            float4 f1 = reinterpret_cast<const float4*>(Ws[w])[row * 16 + c * 2 + 1];
            uint4 pk;
            pk.x = cvt_h2(f0.x, f0.y); pk.y = cvt_h2(f0.z, f0.w);
            pk.z = cvt_h2(f1.x, f1.y); pk.w = cvt_h2(f1.z, f1.w);
            *reinterpret_cast<uint4*>(sm + w * 8192 + row * 128 + ((c ^ (row & 7)) << 4)) = pk;
        }
    }

    const float* ins[3] = {q_in, k_in, v_in};
    __half* outs[3] = {g_qh, g_kh, g_vh};
    const size_t inbase = ((size_t)n * LSEQ + tile * 256) * EMB + (size_t)h * HD;

#pragma unroll 1
    for (int w = 0; w < 3; w++) {
        __syncthreads();   // X free from previous GEMM; weights visible (w=0)

        // ---- load X tile: 256 rows x 64 fp32 -> fp16 swizzled ----
#pragma unroll
        for (int u = 0; u < 8; u++) {
            int cl = tid + u * 256;              // chunk 0..2047
            int row = cl >> 3, c = cl & 7;
            const float4* src = reinterpret_cast<const float4*>(ins[w] + inbase + (size_t)row * EMB);
            float4 f0 = src[c * 2], f1 = src[c * 2 + 1];
            uint4 pk;
            pk.x = cvt_h2(f0.x, f0.y); pk.y = cvt_h2(f0.z, f0.w);
            pk.z = cvt_h2(f1.x, f1.y); pk.w = cvt_h2(f1.z, f1.w);
            *reinterpret_cast<uint4*>(sm + QKV_SMX + row * 128 + ((c ^ (row & 7)) << 4)) = pk;
        }
        __syncthreads();

        // ---- A fragments: 2 m-tiles x 4 k-steps ----
        uint32_t af[2][4][4];
#pragma unroll
        for (int mi = 0; mi < 2; mi++) {
            const int mrow = wid * 32 + mi * 16 + 8 * (lm & 1) + lr;
#pragma unroll
            for (int ks = 0; ks < 4; ks++) {
                const uint32_t addr = smb + QKV_SMX + mrow * 128 +
                    ((((ks << 1) | (lm >> 1)) ^ (mrow & 7)) << 4);
                LDMX4(af[mi][ks][0], af[mi][ks][1], af[mi][ks][2], af[mi][ks][3], addr);
            }
        }

        // ---- GEMM vs weight w ----
        float c[2][8][4];
#pragma unroll
        for (int mi = 0; mi < 2; mi++)
#pragma unroll
            for (int ni = 0; ni < 8; ni++)
#pragma unroll
                for (int j = 0; j < 4; j++) c[mi][ni][j] = 0.f;

#pragma unroll
        for (int ks = 0; ks < 4; ks++) {
#pragma unroll
            for (int np = 0; np < 4; np++) {
                const int wrow = np * 16 + 8 * (lm >> 1) + lr;
                const uint32_t addr = smb + w * 8192 + wrow * 128 +
                    ((((ks << 1) | (lm & 1)) ^ (wrow & 7)) << 4);
                uint32_t bf[4];
                LDMX4(bf[0], bf[1], bf[2], bf[3], addr);
#pragma unroll
                for (int mi = 0; mi < 2; mi++) {
                    mma16816h(c[mi][2*np],   af[mi][ks], bf[0], bf[1]);
                    mma16816h(c[mi][2*np+1], af[mi][ks], bf[2], bf[3]);
                }
            }
        }

        // ---- epilogue: Q linear (scaled), K/V swizzled ----
        uint32_t* out32 = reinterpret_cast<uint32_t*>(outs[w]);
        const int l0 = tile * 256 + wid * 32;
#pragma unroll
        for (int mi = 0; mi < 2; mi++) {
            const int l1 = l0 + mi * 16 + g, l2 = l1 + 8;
            const size_t r1 = ((size_t)bh * LSEQ + l1) * 32;   // uint32 units
            const size_t r2 = ((size_t)bh * LSEQ + l2) * 32;
#pragma unroll
            for (int nt = 0; nt < 8; nt++) {
                float v0 = c[mi][nt][0], v1 = c[mi][nt][1];
                float v2 = c[mi][nt][2], v3 = c[mi][nt][3];
                if (w == 0) { v0 *= QS; v1 *= QS; v2 *= QS; v3 *= QS; }
                if (w == 0) {
                    out32[r1 + 4 * nt + t] = cvt_h2(v0, v1);
                    out32[r2 + 4 * nt + t] = cvt_h2(v2, v3);
                } else {
                    out32[r1 + (((nt ^ (l1 & 7)) << 2) | t)] = cvt_h2(v0, v1);
                    out32[r2 + (((nt ^ (l2 & 7)) << 2) | t)] = cvt_h2(v2, v3);
                }
            }
        }
    }
}

// ---------------------------------------------------------------------------
// Kernel 2: flash attention fp16. 8 warps x 16 q-rows, 2 CTAs/SM.
// S = 1 pass, PV = 1 pass. cp.async.bulk stages (2 x 8KB). (unchanged R10)
// ---------------------------------------------------------------------------
#define ABUF 8192
#define ASTG 16384
#define SM_ATT 32784

__global__ void __launch_bounds__(256, 2) attn_kernel()
{
    extern __shared__ char sm[];
    const uint32_t smb = smem_u32(sm);
    const uint32_t mb[2] = {smb + 32768, smb + 32776};
    const int tid = threadIdx.x, wid = tid >> 5, lane = tid & 31;
    const int g = lane >> 2, t = lane & 3;
    const int bh = blockIdx.y;
    const int q0 = blockIdx.x * 128;
    const int warp_q = q0 + wid * 16;

    const int lm = lane >> 3, lr = lane & 7;
    const int kcb = lm & 1;
    const uint32_t krb = (uint32_t)((8 * (lm >> 1) + lr) * 128);
    const int vcb = lm >> 1;
    const uint32_t vrb = (uint32_t)(((lm & 1) * 8 + lr) * 128);

    if (tid == 0) { MBAR_INIT(mb[0], 1); MBAR_INIT(mb[1], 1); }
    __syncthreads();

    uint32_t qh[4][4];
    {
        const uint32_t* bhp = reinterpret_cast<const uint32_t*>(g_qh) + ((size_t)bh * LSEQ + warp_q) * 32;
#pragma unroll
        for (int ks = 0; ks < 4; ks++) {
            qh[ks][0] = bhp[(size_t)g * 32 + 8*ks + t];
            qh[ks][1] = bhp[(size_t)(g+8) * 32 + 8*ks + t];
            qh[ks][2] = bhp[(size_t)g * 32 + 8*ks + t + 4];
            qh[ks][3] = bhp[(size_t)(g+8) * 32 + 8*ks + t + 4];
        }
    }

    auto issue_stage = [&](int kt, int s) {
        const uint32_t sb = smb + s * ASTG;
        const size_t go = ((size_t)bh * LSEQ + kt * 64) * HD;
        MBAR_EXPECT_TX(mb[s], 2 * ABUF);
        CP_BULK(sb,            (const char*)g_kh + go * 2, ABUF, mb[s]);
        CP_BULK(sb + ABUF,     (const char*)g_vh + go * 2, ABUF, mb[s]);
    };

    float o[8][4];
#pragma unroll
    for (int i = 0; i < 8; i++)
#pragma unroll
        for (int j = 0; j < 4; j++) o[i][j] = 0.f;
    float ls0 = 0.f, ls1 = 0.f;

    if (tid == 0) issue_stage(0, 0);

    for (int kt = 0; kt < 32; kt++) {
        const int s = kt & 1;
        if (kt < 31 && tid == 0) issue_stage(kt + 1, s ^ 1);
        MBAR_WAIT(mb[s], (kt >> 1) & 1);

        const uint32_t KHb = smb + s * ASTG;
        const uint32_t VHb = KHb + ABUF;

#pragma unroll
        for (int half = 0; half < 2; half++) {
            const uint32_t hoff = half * 4096;

            float sc[4][4];
#pragma unroll
            for (int nt = 0; nt < 4; nt++)
#pragma unroll
                for (int j = 0; j < 4; j++) sc[nt][j] = 0.f;

#pragma unroll
            for (int ks = 0; ks < 4; ks++) {
                const uint32_t csw = (uint32_t)((((ks << 1) | kcb) ^ lr) << 4);
                uint32_t kf[8];
                LDMX4(kf[0], kf[1], kf[2], kf[3], KHb + hoff + krb + csw);
                LDMX4(kf[4], kf[5], kf[6], kf[7], KHb + hoff + 2048 + krb + csw);
#pragma unroll
                for (int nt = 0; nt < 4; nt++)
                    mma16816h(sc[nt], qh[ks], kf[2*nt], kf[2*nt+1]);
            }

            uint32_t ph[2][4];
#pragma unroll
            for (int nt = 0; nt < 4; nt++) {
                float p0 = ex2f(sc[nt][0]);
                float p1 = ex2f(sc[nt][1]);
                float p2 = ex2f(sc[nt][2]);
                float p3 = ex2f(sc[nt][3]);
                ls0 += p0 + p1;
                ls1 += p2 + p3;
                const int kc = nt >> 1, su = (nt & 1) * 2;
                ph[kc][su + 0] = cvt_h2(p0, p1);
                ph[kc][su + 1] = cvt_h2(p2, p3);
            }

#pragma unroll
            for (int kc = 0; kc < 2; kc++) {
                const uint32_t kb = hoff + kc * 2048;
#pragma unroll
                for (int db = 0; db < 4; db++) {
                    const uint32_t csw = (uint32_t)((((db << 1) | vcb) ^ lr) << 4);
                    uint32_t vhf[4];
                    LDMX4T(vhf[0], vhf[1], vhf[2], vhf[3], VHb + kb + vrb + csw);
                    mma16816h(o[2*db],   ph[kc], vhf[0], vhf[1]);
                    mma16816h(o[2*db+1], ph[kc], vhf[2], vhf[3]);
                }
            }
        }
        __syncthreads();
    }

    ls0 += __shfl_xor_sync(0xffffffffu, ls0, 1);
    ls0 += __shfl_xor_sync(0xffffffffu, ls0, 2);
    ls1 += __shfl_xor_sync(0xffffffffu, ls1, 1);
    ls1 += __shfl_xor_sync(0xffffffffu, ls1, 2);
    const float inv0 = 1.f / ls0, inv1 = 1.f / ls1;

    const int n = bh >> 4, h = bh & 15;
    const int gt1 = n * LSEQ + warp_q + g;
    const int gt2 = gt1 + 8;
    const int mb1 = gt1 >> 7, mr1 = gt1 & 127;
    const int mb2 = gt2 >> 7, mr2 = gt2 & 127;
#pragma unroll
    for (int nd = 0; nd < 8; nd++) {
        const int dcol = 8 * nd + 2 * t;
        const int kb = h * 2 + (dcol >> 5);
        const int c = dcol & 31;
        const size_t i1 = (((size_t)(mb1 * 32 + kb) * 128 + mr1) * 40 + c) >> 1;
        const size_t i2 = (((size_t)(mb2 * 32 + kb) * 128 + mr2) * 40 + c) >> 1;
        reinterpret_cast<uint32_t*>(g_ao_t)[i1] = cvt_h2(o[nd][0] * inv0, o[nd][1] * inv0);
        reinterpret_cast<uint32_t*>(g_ao_t)[i2] = cvt_h2(o[nd][2] * inv1, o[nd][3] * inv1);
    }
}

// ---------------------------------------------------------------------------
// Kernel 3: output projection, fp16 single-pass, cp.async.bulk, 2 CTAs/SM.
// ---------------------------------------------------------------------------
#define OSTRB 80
#define OBUF  10240
#define OSTG  20480     // 2 buffers: A, W
#define SM_GEMM 40976   // 2 stages + mbars at +40960

__global__ void __launch_bounds__(256, 2) out_proj_kernel(
    const float* __restrict__ bias, float* __restrict__ C)
{
    extern __shared__ char sm[];
    const uint32_t smb = smem_u32(sm);
    const uint32_t mb[2] = {smb + 40960, smb + 40968};
    const int tid = threadIdx.x, wid = tid >> 5, lane = tid & 31;
    const int g = lane >> 2, t = lane & 3;
    const int m0 = blockIdx.y * 128;
    const int n0 = blockIdx.x * 128;
    const int wm = (wid & 3) * 32;
    const int wn = (wid >> 2) * 64;

    if (tid == 0) { MBAR_INIT(mb[0], 1); MBAR_INIT(mb[1], 1); }
    __syncthreads();

    auto issue_stage = [&](int kt, int s) {
        const uint32_t sb = smb + s * OSTG;
        const size_t ao = (size_t)(blockIdx.y * 32 + kt) * (128 * 40);
        const size_t wo = (size_t)(blockIdx.x * 32 + kt) * (128 * 40);
        MBAR_EXPECT_TX(mb[s], 2 * OBUF);
        CP_BULK(sb,           (const char*)g_ao_t + ao * 2, OBUF, mb[s]);
        CP_BULK(sb + OBUF,    (const char*)g_wo_t + wo * 2, OBUF, mb[s]);
    };

    float acc[2][8][4];
#pragma unroll
    for (int i = 0; i < 2; i++)
#pragma unroll
        for (int j = 0; j < 8; j++)
#pragma unroll
            for (int k = 0; k < 4; k++) acc[i][j][k] = 0.f;

    if (tid == 0) issue_stage(0, 0);

    for (int kt = 0; kt < 32; kt++) {
        const int s = kt & 1;
        if (kt < 31 && tid == 0) issue_stage(kt + 1, s ^ 1);
        MBAR_WAIT(mb[s], (kt >> 1) & 1);

        const uint32_t Ao = s * OSTG;
        const uint32_t Bo = Ao + OBUF;

#pragma unroll
        for (int ks = 0; ks < 2; ks++) {
            uint32_t ah[2][4];
#pragma unroll
            for (int mi = 0; mi < 2; mi++) {
                const uint32_t rb = (wm + mi * 16 + g) * OSTRB + ks * 32 + t * 4;
                ah[mi][0] = *reinterpret_cast<const uint32_t*>(sm + Ao + rb);
                ah[mi][1] = *reinterpret_cast<const uint32_t*>(sm + Ao + rb + 8 * OSTRB);
                ah[mi][2] = *reinterpret_cast<const uint32_t*>(sm + Ao + rb + 16);
                ah[mi][3] = *reinterpret_cast<const uint32_t*>(sm + Ao + rb + 8 * OSTRB + 16);
            }
#pragma unroll
            for (int ni = 0; ni < 8; ni++) {
                const uint32_t rb = (wn + ni * 8 + g) * OSTRB + ks * 32 + t * 4;
                uint32_t b0 = *reinterpret_cast<const uint32_t*>(sm + Bo + rb);
                uint32_t b1 = *reinterpret_cast<const uint32_t*>(sm + Bo + rb + 16);
#pragma unroll
                for (int mi = 0; mi < 2; mi++)
                    mma16816h(acc[mi][ni], ah[mi], b0, b1);
            }
        }
        __syncthreads();
    }

#pragma unroll
    for (int mi = 0; mi < 2; mi++) {
        const int r1 = m0 + wm + mi * 16 + g;
        const int r2 = r1 + 8;
#pragma unroll
        for (int ni = 0; ni < 8; ni++) {
            const int col = n0 + wn + ni * 8 + 2 * t;
            float2 bv = *reinterpret_cast<const float2*>(bias + col);
            *reinterpret_cast<float2*>(C + (size_t)r1 * EMB + col) =
                make_float2(acc[mi][ni][0] + bv.x, acc[mi][ni][1] + bv.y);
            *reinterpret_cast<float2*>(C + (size_t)r2 * EMB + col) =
                make_float2(acc[mi][ni][2] + bv.x, acc[mi][ni][3] + bv.y);
        }
    }
}

// ---------------------------------------------------------------------------
extern "C" void kernel_launch(void* const* d_in, const int* in_sizes, int n_in,
                              void* d_out, int out_size)
{
    const float* values  = (const float*)d_in[0];
    const float* keys    = (const float*)d_in[1];
    const float* queries = (const float*)d_in[2];
    const float* Wv      = (const float*)d_in[3];
    const float* Wk      = (const float*)d_in[4];
    const float* Wq      = (const float*)d_in[5];
    const float* Wo      = (const float*)d_in[6];
    const float* bo      = (const float*)d_in[7];
    float* out = (float*)d_out;

    static bool attr_set = false;
    if (!attr_set) {
        cudaFuncSetAttribute(qkv_mma_kernel,
                             cudaFuncAttributeMaxDynamicSharedMemorySize, QKV_SMT);
        cudaFuncSetAttribute(attn_kernel,
                             cudaFuncAttributeMaxDynamicSharedMemorySize, SM_ATT);
        cudaFuncSetAttribute(out_proj_kernel,
                             cudaFuncAttributeMaxDynamicSharedMemorySize, SM_GEMM);
        attr_set = true;
    }

    wo_split_kernel<<<EMB * EMB / 1024, 256>>>(Wo);

    dim3 g1(LSEQ / 256, BHN);
    qkv_mma_kernel<<<g1, 256, QKV_SMT>>>(queries, keys, values, Wq, Wk, Wv);

    dim3 g2(LSEQ / 128, BHN);
    attn_kernel<<<g2, 256, SM_ATT>>>();

    dim3 g3(EMB / 128, (NB * LSEQ) / 128);
    out_proj_kernel<<<g3, 256, SM_GEMM>>>(bo, out);
}

// round 12
// speedup vs baseline: 3.2104x; 1.0384x over previous
#include <cuda_runtime.h>
#include <cuda_fp16.h>
#include <math.h>
#include <stdint.h>

#define NB   4
#define LSEQ 2048
#define EMB  1024
#define NH   16
#define HD   64
#define BHN  (NB*NH)
// Q pre-scale: (1/sqrt(EMB)) * log2(e)  -> scores come out in log2 domain
#define QS   (0.04508422f)
#define HONES 0x3C003C00u     // fp16x2 {1.0, 1.0}

// ---------------- scratch ----------------
__device__ __half g_qh[BHN*LSEQ*HD];          // fp16 [bh][l][d] (pre-scaled, linear)
__device__ __half g_kh[BHN*LSEQ*HD];          // fp16 [bh][l][d] XOR-swizzled chunks
__device__ __half g_vh[BHN*LSEQ*HD];          // fp16, swizzled
// attention out, TILED fp16: [mb 64][kb 32][128 rows][40 half (32 data + 8 pad)]
__device__ __half g_ao_t[64*32*128*40];
// Wo, TILED fp16: [nb 8][kb 32][128][40]
__device__ __half g_wo_t[8*32*128*40];

__device__ __forceinline__ uint32_t cvt_h2(float a, float b) {   // a -> low half
    uint32_t r; asm("cvt.rn.f16x2.f32 %0, %1, %2;" : "=r"(r) : "f"(b), "f"(a)); return r;
}
__device__ __forceinline__ uint32_t ex2_h2(uint32_t s) {
    uint32_t r; asm("ex2.approx.f16x2 %0, %1;" : "=r"(r) : "r"(s)); return r;
}
__device__ __forceinline__ uint32_t smem_u32(const void* p) {
    uint32_t a;
    asm("{ .reg .u64 t; cvta.to.shared.u64 t, %1; cvt.u32.u64 %0, t; }" : "=r"(a) : "l"(p));
    return a;
}
__device__ __forceinline__ void mma16816h(float* c, const uint32_t* a,
                                          uint32_t b0, uint32_t b1) {
    asm volatile("mma.sync.aligned.m16n8k16.row.col.f32.f16.f16.f32 "
        "{%0,%1,%2,%3}, {%4,%5,%6,%7}, {%8,%9}, {%0,%1,%2,%3};"
        : "+f"(c[0]), "+f"(c[1]), "+f"(c[2]), "+f"(c[3])
        : "r"(a[0]), "r"(a[1]), "r"(a[2]), "r"(a[3]), "r"(b0), "r"(b1));
}
#define LDMX4(r0, r1, r2, r3, addr) \
    asm volatile("ldmatrix.sync.aligned.m8n8.x4.shared.b16 {%0,%1,%2,%3}, [%4];" \
        : "=r"(r0), "=r"(r1), "=r"(r2), "=r"(r3) : "r"(addr))
#define LDMX4T(r0, r1, r2, r3, addr) \
    asm volatile("ldmatrix.sync.aligned.m8n8.x4.trans.shared.b16 {%0,%1,%2,%3}, [%4];" \
        : "=r"(r0), "=r"(r1), "=r"(r2), "=r"(r3) : "r"(addr))

#define CP_BULK(dst, src, bytes, mbar) \
    asm volatile("cp.async.bulk.shared::cta.global.mbarrier::complete_tx::bytes [%0], [%1], %2, [%3];" \
        :: "r"(dst), "l"(src), "r"((uint32_t)(bytes)), "r"(mbar) : "memory")
#define MBAR_INIT(a, c) \
    asm volatile("mbarrier.init.shared.b64 [%0], %1;" :: "r"(a), "r"((uint32_t)(c)) : "memory")
#define MBAR_EXPECT_TX(a, tx) \
    asm volatile("mbarrier.arrive.expect_tx.shared.b64 _, [%0], %1;" :: "r"(a), "r"((uint32_t)(tx)) : "memory")
#define MBAR_WAIT(mbar, par) do {                                              \
    uint32_t _m = (mbar), _p = (par), _d;                                      \
    asm volatile("{\n\t.reg .pred p;\n\t"                                      \
        "mbarrier.try_wait.parity.acquire.cta.shared::cta.b64 p, [%1], %2;\n\t"\
        "selp.b32 %0, 1, 0, p;\n\t}" : "=r"(_d) : "r"(_m), "r"(_p) : "memory");\
    if (!_d) {                                                                 \
        asm volatile("{\n\t.reg .pred P1;\n\t"                                 \
            "W_%=:\n\t"                                                        \
            "mbarrier.try_wait.parity.acquire.cta.shared::cta.b64 P1, [%0], %1, 0x989680;\n\t" \
            "@P1 bra.uni D_%=;\n\t"                                            \
            "bra.uni W_%=;\n\t"                                                \
            "D_%=:\n\t}" :: "r"(_m), "r"(_p) : "memory");                      \
    }                                                                          \
} while (0)

// ---------------------------------------------------------------------------
// Kernel 0: Wo (fp32) -> fp16 TILED [nb][kb][128][40]
// ---------------------------------------------------------------------------
__global__ void __launch_bounds__(256) wo_split_kernel(const float* __restrict__ Wo)
{
    const int i4 = (blockIdx.x * 256 + threadIdx.x) * 4;
    const int e = i4 >> 10, k = i4 & 1023;
    float4 w = *reinterpret_cast<const float4*>(Wo + i4);
    const int nb = e >> 7, er = e & 127, kb = k >> 5, c = k & 31;
    const size_t base = ((size_t)(nb * 32 + kb) * 128 + er) * 40 + c;
    uint32_t* oh = reinterpret_cast<uint32_t*>(g_wo_t + base);
    oh[0] = cvt_h2(w.x, w.y); oh[1] = cvt_h2(w.z, w.w);
}

// ---------------------------------------------------------------------------
// Kernel 1: QKV projection on HMMA (unchanged from R11)
// ---------------------------------------------------------------------------
#define QKV_SMX 24576
#define QKV_SMT 57344

__global__ void __launch_bounds__(256) qkv_mma_kernel(
    const float* __restrict__ q_in, const float* __restrict__ k_in,
    const float* __restrict__ v_in,
    const float* __restrict__ Wq, const float* __restrict__ Wk,
    const float* __restrict__ Wv)
{
    extern __shared__ char sm[];
    const uint32_t smb = smem_u32(sm);
    const int tid = threadIdx.x, wid = tid >> 5, lane = tid & 31;
    const int g = lane >> 2, t = lane & 3;
    const int lm = lane >> 3, lr = lane & 7;
    const int bh = blockIdx.y;
    const int tile = blockIdx.x;
    const int n = bh >> 4, h = bh & 15;

    const float* Ws[3] = {Wq, Wk, Wv};
#pragma unroll
    for (int w = 0; w < 3; w++) {
#pragma unroll
        for (int u = 0; u < 2; u++) {
            int cl = tid + u * 256;
            int row = cl >> 3, c = cl & 7;
            float4 f0 = reinterpret_cast<const float4*>(Ws[w])[row * 16 + c * 2];
            float4 f1 = reinterpret_cast<const float4*>(Ws[w])[row * 16 + c * 2 + 1];
            uint4 pk;
            pk.x = cvt_h2(f0.x, f0.y); pk.y = cvt_h2(f0.z, f0.w);
            pk.z = cvt_h2(f1.x, f1.y); pk.w = cvt_h2(f1.z, f1.w);
            *reinterpret_cast<uint4*>(sm + w * 8192 + row * 128 + ((c ^ (row & 7)) << 4)) = pk;
        }
    }

    const float* ins[3] = {q_in, k_in, v_in};
    __half* outs[3] = {g_qh, g_kh, g_vh};
    const size_t inbase = ((size_t)n * LSEQ + tile * 256) * EMB + (size_t)h * HD;

#pragma unroll 1
    for (int w = 0; w < 3; w++) {
        __syncthreads();

#pragma unroll
        for (int u = 0; u < 8; u++) {
            int cl = tid + u * 256;
            int row = cl >> 3, c = cl & 7;
            const float4* src = reinterpret_cast<const float4*>(ins[w] + inbase + (size_t)row * EMB);
            float4 f0 = src[c * 2], f1 = src[c * 2 + 1];
            uint4 pk;
            pk.x = cvt_h2(f0.x, f0.y); pk.y = cvt_h2(f0.z, f0.w);
            pk.z = cvt_h2(f1.x, f1.y); pk.w = cvt_h2(f1.z, f1.w);
            *reinterpret_cast<uint4*>(sm + QKV_SMX + row * 128 + ((c ^ (row & 7)) << 4)) = pk;
        }
        __syncthreads();

        uint32_t af[2][4][4];
#pragma unroll
        for (int mi = 0; mi < 2; mi++) {
            const int mrow = wid * 32 + mi * 16 + 8 * (lm & 1) + lr;
#pragma unroll
            for (int ks = 0; ks < 4; ks++) {
                const uint32_t addr = smb + QKV_SMX + mrow * 128 +
                    ((((ks << 1) | (lm >> 1)) ^ (mrow & 7)) << 4);
                LDMX4(af[mi][ks][0], af[mi][ks][1], af[mi][ks][2], af[mi][ks][3], addr);
            }
        }

        float c[2][8][4];
#pragma unroll
        for (int mi = 0; mi < 2; mi++)
#pragma unroll
            for (int ni = 0; ni < 8; ni++)
#pragma unroll
                for (int j = 0; j < 4; j++) c[mi][ni][j] = 0.f;

#pragma unroll
        for (int ks = 0; ks < 4; ks++) {
#pragma unroll
            for (int np = 0; np < 4; np++) {
                const int wrow = np * 16 + 8 * (lm >> 1) + lr;
                const uint32_t addr = smb + w * 8192 + wrow * 128 +
                    ((((ks << 1) | (lm & 1)) ^ (wrow & 7)) << 4);
                uint32_t bf[4];
                LDMX4(bf[0], bf[1], bf[2], bf[3], addr);
#pragma unroll
                for (int mi = 0; mi < 2; mi++) {
                    mma16816h(c[mi][2*np],   af[mi][ks], bf[0], bf[1]);
                    mma16816h(c[mi][2*np+1], af[mi][ks], bf[2], bf[3]);
                }
            }
        }

        uint32_t* out32 = reinterpret_cast<uint32_t*>(outs[w]);
        const int l0 = tile * 256 + wid * 32;
#pragma unroll
        for (int mi = 0; mi < 2; mi++) {
            const int l1 = l0 + mi * 16 + g, l2 = l1 + 8;
            const size_t r1 = ((size_t)bh * LSEQ + l1) * 32;
            const size_t r2 = ((size_t)bh * LSEQ + l2) * 32;
#pragma unroll
            for (int nt = 0; nt < 8; nt++) {
                float v0 = c[mi][nt][0], v1 = c[mi][nt][1];
                float v2 = c[mi][nt][2], v3 = c[mi][nt][3];
                if (w == 0) { v0 *= QS; v1 *= QS; v2 *= QS; v3 *= QS; }
                if (w == 0) {
                    out32[r1 + 4 * nt + t] = cvt_h2(v0, v1);
                    out32[r2 + 4 * nt + t] = cvt_h2(v2, v3);
                } else {
                    out32[r1 + (((nt ^ (l1 & 7)) << 2) | t)] = cvt_h2(v0, v1);
                    out32[r2 + (((nt ^ (l2 & 7)) << 2) | t)] = cvt_h2(v2, v3);
                }
            }
        }
    }
}

// ---------------------------------------------------------------------------
// Kernel 2: flash attention fp16, ex2.f16x2 softmax, lsum via P*ones MMA.
// ---------------------------------------------------------------------------
#define ABUF 8192
#define ASTG 16384
#define SM_ATT 32784

__global__ void __launch_bounds__(256, 2) attn_kernel()
{
    extern __shared__ char sm[];
    const uint32_t smb = smem_u32(sm);
    const uint32_t mb[2] = {smb + 32768, smb + 32776};
    const int tid = threadIdx.x, wid = tid >> 5, lane = tid & 31;
    const int g = lane >> 2, t = lane & 3;
    const int bh = blockIdx.y;
    const int q0 = blockIdx.x * 128;
    const int warp_q = q0 + wid * 16;

    const int lm = lane >> 3, lr = lane & 7;
    const int kcb = lm & 1;
    const uint32_t krb = (uint32_t)((8 * (lm >> 1) + lr) * 128);
    const int vcb = lm >> 1;
    const uint32_t vrb = (uint32_t)(((lm & 1) * 8 + lr) * 128);

    if (tid == 0) { MBAR_INIT(mb[0], 1); MBAR_INIT(mb[1], 1); }
    __syncthreads();

    uint32_t qh[4][4];
    {
        const uint32_t* bhp = reinterpret_cast<const uint32_t*>(g_qh) + ((size_t)bh * LSEQ + warp_q) * 32;
#pragma unroll
        for (int ks = 0; ks < 4; ks++) {
            qh[ks][0] = bhp[(size_t)g * 32 + 8*ks + t];
            qh[ks][1] = bhp[(size_t)(g+8) * 32 + 8*ks + t];
            qh[ks][2] = bhp[(size_t)g * 32 + 8*ks + t + 4];
            qh[ks][3] = bhp[(size_t)(g+8) * 32 + 8*ks + t + 4];
        }
    }

    auto issue_stage = [&](int kt, int s) {
        const uint32_t sb = smb + s * ASTG;
        const size_t go = ((size_t)bh * LSEQ + kt * 64) * HD;
        MBAR_EXPECT_TX(mb[s], 2 * ABUF);
        CP_BULK(sb,            (const char*)g_kh + go * 2, ABUF, mb[s]);
        CP_BULK(sb + ABUF,     (const char*)g_vh + go * 2, ABUF, mb[s]);
    };

    float o[8][4];
#pragma unroll
    for (int i = 0; i < 8; i++)
#pragma unroll
        for (int j = 0; j < 4; j++) o[i][j] = 0.f;
    float lsacc[4] = {0.f, 0.f, 0.f, 0.f};

    if (tid == 0) issue_stage(0, 0);

    for (int kt = 0; kt < 32; kt++) {
        const int s = kt & 1;
        if (kt < 31 && tid == 0) issue_stage(kt + 1, s ^ 1);
        MBAR_WAIT(mb[s], (kt >> 1) & 1);

        const uint32_t KHb = smb + s * ASTG;
        const uint32_t VHb = KHb + ABUF;

#pragma unroll
        for (int half = 0; half < 2; half++) {
            const uint32_t hoff = half * 4096;

            float sc[4][4];
#pragma unroll
            for (int nt = 0; nt < 4; nt++)
#pragma unroll
                for (int j = 0; j < 4; j++) sc[nt][j] = 0.f;

#pragma unroll
            for (int ks = 0; ks < 4; ks++) {
                const uint32_t csw = (uint32_t)((((ks << 1) | kcb) ^ lr) << 4);
                uint32_t kf[8];
                LDMX4(kf[0], kf[1], kf[2], kf[3], KHb + hoff + krb + csw);
                LDMX4(kf[4], kf[5], kf[6], kf[7], KHb + hoff + 2048 + krb + csw);
#pragma unroll
                for (int nt = 0; nt < 4; nt++)
                    mma16816h(sc[nt], qh[ks], kf[2*nt], kf[2*nt+1]);
            }

            // ---- softmax: pack scores fp16x2, packed exp2 -> P fragments ----
            uint32_t ph[2][4];
#pragma unroll
            for (int nt = 0; nt < 4; nt++) {
                const int kc = nt >> 1, su = (nt & 1) * 2;
                ph[kc][su + 0] = ex2_h2(cvt_h2(sc[nt][0], sc[nt][1]));
                ph[kc][su + 1] = ex2_h2(cvt_h2(sc[nt][2], sc[nt][3]));
            }

            // ---- PV (1 pass) + lsum via P*ones MMA ----
#pragma unroll
            for (int kc = 0; kc < 2; kc++) {
                const uint32_t kb = hoff + kc * 2048;
#pragma unroll
                for (int db = 0; db < 4; db++) {
                    const uint32_t csw = (uint32_t)((((db << 1) | vcb) ^ lr) << 4);
                    uint32_t vhf[4];
                    LDMX4T(vhf[0], vhf[1], vhf[2], vhf[3], VHb + kb + vrb + csw);
                    mma16816h(o[2*db],   ph[kc], vhf[0], vhf[1]);
                    mma16816h(o[2*db+1], ph[kc], vhf[2], vhf[3]);
                }
                mma16816h(lsacc, ph[kc], HONES, HONES);   // row sums, exact fp32
            }
        }
        __syncthreads();
    }

    // ---- epilogue: normalize (row sums already complete per thread) ----
    const float inv0 = 1.f / lsacc[0], inv1 = 1.f / lsacc[2];

    const int n = bh >> 4, h = bh & 15;
    const int gt1 = n * LSEQ + warp_q + g;
    const int gt2 = gt1 + 8;
    const int mb1 = gt1 >> 7, mr1 = gt1 & 127;
    const int mb2 = gt2 >> 7, mr2 = gt2 & 127;
#pragma unroll
    for (int nd = 0; nd < 8; nd++) {
        const int dcol = 8 * nd + 2 * t;
        const int kb = h * 2 + (dcol >> 5);
        const int c = dcol & 31;
        const size_t i1 = (((size_t)(mb1 * 32 + kb) * 128 + mr1) * 40 + c) >> 1;
        const size_t i2 = (((size_t)(mb2 * 32 + kb) * 128 + mr2) * 40 + c) >> 1;
        reinterpret_cast<uint32_t*>(g_ao_t)[i1] = cvt_h2(o[nd][0] * inv0, o[nd][1] * inv0);
        reinterpret_cast<uint32_t*>(g_ao_t)[i2] = cvt_h2(o[nd][2] * inv1, o[nd][3] * inv1);
    }
}

// ---------------------------------------------------------------------------
// Kernel 3: output projection, fp16 single-pass, ldmatrix fragments.
// ---------------------------------------------------------------------------
#define OSTRB 80
#define OBUF  10240
#define OSTG  20480
#define SM_GEMM 40976

__global__ void __launch_bounds__(256, 2) out_proj_kernel(
    const float* __restrict__ bias, float* __restrict__ C)
{
    extern __shared__ char sm[];
    const uint32_t smb = smem_u32(sm);
    const uint32_t mb[2] = {smb + 40960, smb + 40968};
    const int tid = threadIdx.x, wid = tid >> 5, lane = tid & 31;
    const int g = lane >> 2, t = lane & 3;
    const int lm = lane >> 3, lr = lane & 7;
    const int m0 = blockIdx.y * 128;
    const int n0 = blockIdx.x * 128;
    const int wm = (wid & 3) * 32;
    const int wn = (wid >> 2) * 64;

    // ldmatrix lane offsets (stride-80B rows, conflict-free: 20r mod 32 distinct)
    // A: matrices {rows+0,c0},{rows+8,c0},{rows+0,c16},{rows+8,c16}
    const uint32_t a_lmo = (uint32_t)(((lm & 1) * 8 + lr) * OSTRB + (lm >> 1) * 16);
    // B: matrices {ni,c0},{ni,c16},{ni+1,c0},{ni+1,c16}
    const uint32_t b_lmo = (uint32_t)(((lm >> 1) * 8 + lr) * OSTRB + (lm & 1) * 16);

    if (tid == 0) { MBAR_INIT(mb[0], 1); MBAR_INIT(mb[1], 1); }
    __syncthreads();

    auto issue_stage = [&](int kt, int s) {
        const uint32_t sb = smb + s * OSTG;
        const size_t ao = (size_t)(blockIdx.y * 32 + kt) * (128 * 40);
        const size_t wo = (size_t)(blockIdx.x * 32 + kt) * (128 * 40);
        MBAR_EXPECT_TX(mb[s], 2 * OBUF);
        CP_BULK(sb,           (const char*)g_ao_t + ao * 2, OBUF, mb[s]);
        CP_BULK(sb + OBUF,    (const char*)g_wo_t + wo * 2, OBUF, mb[s]);
    };

    float acc[2][8][4];
#pragma unroll
    for (int i = 0; i < 2; i++)
#pragma unroll
        for (int j = 0; j < 8; j++)
#pragma unroll
            for (int k = 0; k < 4; k++) acc[i][j][k] = 0.f;

    if (tid == 0) issue_stage(0, 0);

    for (int kt = 0; kt < 32; kt++) {
        const int s = kt & 1;
        if (kt < 31 && tid == 0) issue_stage(kt + 1, s ^ 1);
        MBAR_WAIT(mb[s], (kt >> 1) & 1);

        const uint32_t Ao = smb + s * OSTG;
        const uint32_t Bo = Ao + OBUF;

#pragma unroll
        for (int ks = 0; ks < 2; ks++) {
            uint32_t ah[2][4];
#pragma unroll
            for (int mi = 0; mi < 2; mi++)
                LDMX4(ah[mi][0], ah[mi][1], ah[mi][2], ah[mi][3],
                      Ao + (wm + mi * 16) * OSTRB + ks * 32 + a_lmo);
#pragma unroll
            for (int ni = 0; ni < 8; ni += 2) {
                uint32_t bf[4];
                LDMX4(bf[0], bf[1], bf[2], bf[3],
                      Bo + (wn + ni * 8) * OSTRB + ks * 32 + b_lmo);
#pragma unroll
                for (int mi = 0; mi < 2; mi++) {
                    mma16816h(acc[mi][ni],     ah[mi], bf[0], bf[1]);
                    mma16816h(acc[mi][ni + 1], ah[mi], bf[2], bf[3]);
                }
            }
        }
        __syncthreads();
    }

#pragma unroll
    for (int mi = 0; mi < 2; mi++) {
        const int r1 = m0 + wm + mi * 16 + g;
        const int r2 = r1 + 8;
#pragma unroll
        for (int ni = 0; ni < 8; ni++) {
            const int col = n0 + wn + ni * 8 + 2 * t;
            float2 bv = *reinterpret_cast<const float2*>(bias + col);
            *reinterpret_cast<float2*>(C + (size_t)r1 * EMB + col) =
                make_float2(acc[mi][ni][0] + bv.x, acc[mi][ni][1] + bv.y);
            *reinterpret_cast<float2*>(C + (size_t)r2 * EMB + col) =
                make_float2(acc[mi][ni][2] + bv.x, acc[mi][ni][3] + bv.y);
        }
    }
}

// ---------------------------------------------------------------------------
extern "C" void kernel_launch(void* const* d_in, const int* in_sizes, int n_in,
                              void* d_out, int out_size)
{
    const float* values  = (const float*)d_in[0];
    const float* keys    = (const float*)d_in[1];
    const float* queries = (const float*)d_in[2];
    const float* Wv      = (const float*)d_in[3];
    const float* Wk      = (const float*)d_in[4];
    const float* Wq      = (const float*)d_in[5];
    const float* Wo      = (const float*)d_in[6];
    const float* bo      = (const float*)d_in[7];
    float* out = (float*)d_out;

    static bool attr_set = false;
    if (!attr_set) {
        cudaFuncSetAttribute(qkv_mma_kernel,
                             cudaFuncAttributeMaxDynamicSharedMemorySize, QKV_SMT);
        cudaFuncSetAttribute(attn_kernel,
                             cudaFuncAttributeMaxDynamicSharedMemorySize, SM_ATT);
        cudaFuncSetAttribute(out_proj_kernel,
                             cudaFuncAttributeMaxDynamicSharedMemorySize, SM_GEMM);
        attr_set = true;
    }

    wo_split_kernel<<<EMB * EMB / 1024, 256>>>(Wo);

    dim3 g1(LSEQ / 256, BHN);
    qkv_mma_kernel<<<g1, 256, QKV_SMT>>>(queries, keys, values, Wq, Wk, Wv);

    dim3 g2(LSEQ / 128, BHN);
    attn_kernel<<<g2, 256, SM_ATT>>>();

    dim3 g3(EMB / 128, (NB * LSEQ) / 128);
    out_proj_kernel<<<g3, 256, SM_GEMM>>>(bo, out);
}